// round 1
// baseline (speedup 1.0000x reference)
#include <cuda_runtime.h>
#include <math_constants.h>

#define NN 512
#define BB 4
#define HH 4
#define FF 64
#define NCHUNK 32   // i-chunks per (b,h) in attention, 16 rows each

// ---------------- scratch (device globals; no allocation) ----------------
__device__ float g_d[NN];                       // rsqrt degrees
__device__ float g_c[NN];                       // col sums of noradj
__device__ float g_nor[NN * NN];                // noradj[i][j]
__device__ float g_norT[NN * NN];               // noradj[j][i]
__device__ float g_q[BB * HH * NN * FF];        // [bh][n][f]
__device__ float g_kT[BB * HH * FF * NN];       // [bh][f][n]
__device__ float g_Tpart[NCHUNK * BB * HH * NN];// per-chunk partials (deterministic)
__device__ float g_T[BB * HH * NN];             // reduced T[bh][j]
__device__ float g_sx[BB * NN * FF];            // x * S

// ---------------- helpers ----------------
__device__ __forceinline__ float blockReduceSum256(float v, float* red) {
    #pragma unroll
    for (int o = 16; o; o >>= 1) v += __shfl_xor_sync(0xffffffffu, v, o);
    int wid = threadIdx.x >> 5, lane = threadIdx.x & 31;
    if (lane == 0) red[wid] = v;
    __syncthreads();
    float r = (threadIdx.x < 8) ? red[threadIdx.x] : 0.f;
    if (wid == 0) {
        #pragma unroll
        for (int o = 4; o; o >>= 1) r += __shfl_xor_sync(0xffffffffu, r, o);
    }
    return r;  // valid in thread 0
}

// ---------------- K1a: degrees ----------------
__global__ void k_deg(const float* __restrict__ adj) {
    __shared__ float red[8];
    int i = blockIdx.x;
    float s = 0.f;
    for (int j = threadIdx.x; j < NN; j += 256) s += adj[i * NN + j];
    s = blockReduceSum256(s, red);
    if (threadIdx.x == 0) g_d[i] = rsqrtf(s + 1.0f);
}

// ---------------- K1b: normalized adjacency (+transpose) ----------------
__global__ void k_nor(const float* __restrict__ adj) {
    int i = blockIdx.x;
    int j = threadIdx.x;
    float a = adj[i * NN + j] + (i == j ? 1.0f : 0.0f);
    float v = g_d[i] * g_d[j] * a;
    g_nor[i * NN + j] = v;
    g_norT[j * NN + i] = v;
}

// ---------------- K2: q/k projections with layout scatter ----------------
// grid (64, 2): blockIdx.y==0 -> q, ==1 -> k. 256 threads, 32 x-rows per block.
__global__ __launch_bounds__(256) void k_proj(const float* __restrict__ x,
                                              const float* __restrict__ Wq,
                                              const float* __restrict__ bq,
                                              const float* __restrict__ Wk,
                                              const float* __restrict__ bk) {
    const float* W = blockIdx.y ? Wk : Wq;
    const float* bias = blockIdx.y ? bk : bq;
    const int c = threadIdx.x;            // output column 0..255
    __shared__ float xs[32][64];
    const int rowBase = blockIdx.x * 32;
    for (int t = threadIdx.x; t < 32 * 64; t += 256)
        ((float*)xs)[t] = x[rowBase * 64 + t];
    float w[64];
    #pragma unroll
    for (int f = 0; f < 64; f++) w[f] = W[f * 256 + c];
    const float bv = bias[c];
    __syncthreads();
    const int h = c >> 6, fo = c & 63;
    for (int r = 0; r < 32; r++) {
        float acc = bv;
        #pragma unroll
        for (int f = 0; f < 64; f++) acc += xs[r][f] * w[f];
        int row = rowBase + r;
        int b = row >> 9, n = row & 511;
        int bh = b * HH + h;
        if (blockIdx.y == 0) g_q[(bh * NN + n) * FF + fo] = acc;
        else                 g_kT[(bh * FF + fo) * NN + n] = acc;
    }
}

// ---------------- K3: scores + softmax + noradj-weighted reduce ----------------
// grid (NCHUNK, H, B), 512 threads (one per column j). k column lives in 32
// packed f32x2 registers; dot product uses Blackwell fma.rn.f32x2.
__global__ __launch_bounds__(512, 1) void k_attn() {
    const int chunk = blockIdx.x, h = blockIdx.y, b = blockIdx.z;
    const int bh = b * HH + h;
    const int j = threadIdx.x;
    const float* kT = g_kT + bh * FF * NN;

    unsigned long long kreg[32];
    #pragma unroll
    for (int p = 0; p < 32; p++) {
        float lo = kT[(2 * p) * NN + j];
        float hi = kT[(2 * p + 1) * NN + j];
        asm("mov.b64 %0,{%1,%2};" : "=l"(kreg[p]) : "f"(lo), "f"(hi));
    }

    __shared__ __align__(16) float qs[16][64];
    __shared__ float red[16];
    __shared__ float bcast[2];
    const int iBase = chunk * 16;
    const float* qp = g_q + (bh * NN + iBase) * FF;
    for (int t = threadIdx.x; t < 16 * 64; t += 512) ((float*)qs)[t] = qp[t];
    __syncthreads();

    const int wid = threadIdx.x >> 5, lane = threadIdx.x & 31;
    float acc = 0.f;

    for (int il = 0; il < 16; il++) {
        const double2* q2 = (const double2*)(&qs[il][0]);
        unsigned long long aA = 0ull, aB = 0ull;
        #pragma unroll
        for (int p = 0; p < 16; p++) {
            double2 qq = q2[p];
            unsigned long long qa = __double_as_longlong(qq.x);
            unsigned long long qb = __double_as_longlong(qq.y);
            asm("fma.rn.f32x2 %0,%1,%2,%0;" : "+l"(aA) : "l"(qa), "l"(kreg[2 * p]));
            asm("fma.rn.f32x2 %0,%1,%2,%0;" : "+l"(aB) : "l"(qb), "l"(kreg[2 * p + 1]));
        }
        float a0, a1, b0, b1;
        asm("mov.b64 {%0,%1},%2;" : "=f"(a0), "=f"(a1) : "l"(aA));
        asm("mov.b64 {%0,%1},%2;" : "=f"(b0), "=f"(b1) : "l"(aB));
        float s = ((a0 + b0) + (a1 + b1)) * 0.125f;  // / sqrt(64)

        // block max over 512
        float m = s;
        #pragma unroll
        for (int o = 16; o; o >>= 1) m = fmaxf(m, __shfl_xor_sync(0xffffffffu, m, o));
        if (lane == 0) red[wid] = m;
        __syncthreads();
        if (wid == 0) {
            float v = (lane < 16) ? red[lane] : -CUDART_INF_F;
            #pragma unroll
            for (int o = 8; o; o >>= 1) v = fmaxf(v, __shfl_xor_sync(0xffffffffu, v, o));
            if (lane == 0) bcast[0] = v;
        }
        __syncthreads();

        float e = __expf(s - bcast[0]);

        // block sum over 512
        float t = e;
        #pragma unroll
        for (int o = 16; o; o >>= 1) t += __shfl_xor_sync(0xffffffffu, t, o);
        if (lane == 0) red[wid] = t;
        __syncthreads();
        if (wid == 0) {
            float v = (lane < 16) ? red[lane] : 0.f;
            #pragma unroll
            for (int o = 8; o; o >>= 1) v += __shfl_xor_sync(0xffffffffu, v, o);
            if (lane == 0) bcast[1] = v;
        }
        __syncthreads();

        float attn = e / bcast[1];
        acc += g_nor[(iBase + il) * NN + j] * attn;
    }
    g_Tpart[chunk * (BB * HH * NN) + bh * NN + j] = acc;
}

// ---------------- K3b: reduce T partials + column sums c ----------------
// grid 512+32 blocks of 256 threads.
__global__ void k_red() {
    if (blockIdx.x < NN) {
        __shared__ float red[8];
        int j = blockIdx.x;
        float s = 0.f;
        for (int i = threadIdx.x; i < NN; i += 256) s += g_norT[j * NN + i];
        s = blockReduceSum256(s, red);
        if (threadIdx.x == 0) g_c[j] = s;
    } else {
        int v = (blockIdx.x - NN) * 256 + threadIdx.x;  // 0..8191
        float s = 0.f;
        #pragma unroll
        for (int ch = 0; ch < NCHUNK; ch++) s += g_Tpart[ch * (BB * HH * NN) + v];
        g_T[v] = s;
    }
}

// ---------------- K4a: S and sx ----------------
__global__ void k_sx(const float* __restrict__ x,
                     const float* __restrict__ Wlin,
                     const float* __restrict__ blin) {
    int idx = blockIdx.x * 256 + threadIdx.x;  // over B*N*F = 131072
    int f = idx & 63, j = (idx >> 6) & 511, b = idx >> 15;
    float s = g_c[j] * blin[f];
    #pragma unroll
    for (int h = 0; h < HH; h++) s += g_T[(b * HH + h) * NN + j] * Wlin[h * FF + f];
    g_sx[idx] = x[idx] * s;
}

// ---------------- K4b: out = relu((noradj @ sx) @ Wfc + bfc) ----------------
// grid (32, B), 1024 threads = 16 i-rows x 64 f.
__global__ __launch_bounds__(1024) void k_out(const float* __restrict__ Wfc,
                                              const float* __restrict__ bfc,
                                              float* __restrict__ out) {
    const int iBase = blockIdx.x * 16;
    const int b = blockIdx.y;
    const int il = threadIdx.x >> 6, f = threadIdx.x & 63;

    __shared__ float sxs[8][64];
    __shared__ float nrs[8][16];
    __shared__ float tmp[16][65];

    float acc = 0.f;
    for (int j0 = 0; j0 < NN; j0 += 8) {
        if (threadIdx.x < 512) {
            ((float*)sxs)[threadIdx.x] = g_sx[(b * NN + j0) * FF + threadIdx.x];
        } else if (threadIdx.x < 640) {
            int t = threadIdx.x - 512;
            int jj = t >> 4, ii = t & 15;
            nrs[jj][ii] = g_norT[(j0 + jj) * NN + iBase + ii];
        }
        __syncthreads();
        #pragma unroll
        for (int jj = 0; jj < 8; jj++) acc += nrs[jj][il] * sxs[jj][f];
        __syncthreads();
    }

    tmp[il][f] = acc;
    __syncthreads();
    float o = bfc[f];
    #pragma unroll
    for (int ff = 0; ff < 64; ff++) o += tmp[il][ff] * Wfc[ff * 64 + f];
    out[((b * NN) + iBase + il) * FF + f] = fmaxf(o, 0.f);
}

// ---------------- launch ----------------
extern "C" void kernel_launch(void* const* d_in, const int* in_sizes, int n_in,
                              void* d_out, int out_size) {
    const float* x    = (const float*)d_in[0];
    const float* adj  = (const float*)d_in[1];
    const float* Wq   = (const float*)d_in[2];
    const float* bq   = (const float*)d_in[3];
    const float* Wk   = (const float*)d_in[4];
    const float* bk   = (const float*)d_in[5];
    const float* Wlin = (const float*)d_in[6];
    const float* blin = (const float*)d_in[7];
    const float* Wfc  = (const float*)d_in[8];
    const float* bfc  = (const float*)d_in[9];
    float* out = (float*)d_out;

    k_deg<<<NN, 256>>>(adj);
    k_nor<<<NN, NN>>>(adj);
    k_proj<<<dim3(64, 2), 256>>>(x, Wq, bq, Wk, bk);
    k_attn<<<dim3(NCHUNK, HH, BB), 512>>>();
    k_red<<<NN + 32, 256>>>();
    k_sx<<<512, 256>>>(x, Wlin, blin);
    k_out<<<dim3(32, BB), 1024>>>(Wfc, bfc, out);
}

// round 2
// speedup vs baseline: 1.5318x; 1.5318x over previous
#include <cuda_runtime.h>
#include <math_constants.h>

#define NN 512
#define BB 4
#define HH 4
#define FF 64
#define NCHUNK 32   // i-chunks per (b,h) in attention, 16 rows each

// ---------------- scratch (device globals; no allocation) ----------------
__device__ float g_d[NN];                       // rsqrt degrees
__device__ float g_c[NN];                       // col sums of noradj
__device__ float g_cpart[32 * NN];              // col-sum partials
__device__ float g_nor[NN * NN];                // noradj[i][j]
__device__ float g_q[BB * HH * NN * FF];        // [bh][n][f]
__device__ float g_kT[BB * HH * FF * NN];       // [bh][f][n]
__device__ float g_Tpart[NCHUNK * BB * HH * NN];// per-chunk partials (deterministic)
__device__ float g_T[BB * HH * NN];             // reduced T[bh][j]
__device__ float g_sx[BB * NN * FF];            // x * S

// ---------------- helpers ----------------
__device__ __forceinline__ float blockReduceSum256(float v, float* red) {
    #pragma unroll
    for (int o = 16; o; o >>= 1) v += __shfl_xor_sync(0xffffffffu, v, o);
    int wid = threadIdx.x >> 5, lane = threadIdx.x & 31;
    if (lane == 0) red[wid] = v;
    __syncthreads();
    float r = (threadIdx.x < 8) ? red[threadIdx.x] : 0.f;
    if (wid == 0) {
        #pragma unroll
        for (int o = 4; o; o >>= 1) r += __shfl_xor_sync(0xffffffffu, r, o);
    }
    return r;  // valid in thread 0
}

// ---------------- K1a: degrees ----------------
__global__ void k_deg(const float* __restrict__ adj) {
    __shared__ float red[8];
    int i = blockIdx.x;
    float s = 0.f;
    for (int j = threadIdx.x; j < NN; j += 256) s += adj[i * NN + j];
    s = blockReduceSum256(s, red);
    if (threadIdx.x == 0) g_d[i] = rsqrtf(s + 1.0f);
}

// ---------------- K1b: normalized adjacency (coalesced only) ----------------
__global__ void k_nor(const float* __restrict__ adj) {
    int i = blockIdx.x;
    int j = threadIdx.x;
    float a = adj[i * NN + j] + (i == j ? 1.0f : 0.0f);
    g_nor[i * NN + j] = g_d[i] * g_d[j] * a;
}

// ---------------- K1c: column-sum partials (coalesced) ----------------
__global__ void k_csum() {
    int bk = blockIdx.x;                 // 0..31, rows [16bk, 16bk+16)
    int j = threadIdx.x;                 // 0..511
    float s = 0.f;
    #pragma unroll
    for (int r = 0; r < 16; r++) s += g_nor[(bk * 16 + r) * NN + j];
    g_cpart[bk * NN + j] = s;
}

// ---------------- K2: q/k projections with layout scatter ----------------
__global__ __launch_bounds__(256) void k_proj(const float* __restrict__ x,
                                              const float* __restrict__ Wq,
                                              const float* __restrict__ bq,
                                              const float* __restrict__ Wk,
                                              const float* __restrict__ bk) {
    const float* W = blockIdx.y ? Wk : Wq;
    const float* bias = blockIdx.y ? bk : bq;
    const int c = threadIdx.x;            // output column 0..255
    __shared__ float xs[32][64];
    const int rowBase = blockIdx.x * 32;
    for (int t = threadIdx.x; t < 32 * 64; t += 256)
        ((float*)xs)[t] = x[rowBase * 64 + t];
    float w[64];
    #pragma unroll
    for (int f = 0; f < 64; f++) w[f] = W[f * 256 + c];
    const float bv = bias[c];
    __syncthreads();
    const int h = c >> 6, fo = c & 63;
    for (int r = 0; r < 32; r++) {
        float acc = bv;
        #pragma unroll
        for (int f = 0; f < 64; f++) acc += xs[r][f] * w[f];
        int row = rowBase + r;
        int b = row >> 9, n = row & 511;
        int bh = b * HH + h;
        if (blockIdx.y == 0) g_q[(bh * NN + n) * FF + fo] = acc;
        else                 g_kT[(bh * FF + fo) * NN + n] = acc;
    }
}

// ---------------- K3: scores + batched softmax + noradj-weighted reduce ----
// grid (NCHUNK, H, B), 512 threads (one per column j). 16 rows per block.
// All 16 dots computed first (pure ILP), then ONE batched 2-stage reduction
// for the 16 maxima and one for the 16 sums: 4 __syncthreads total.
__global__ __launch_bounds__(512, 1) void k_attn() {
    const int chunk = blockIdx.x, h = blockIdx.y, b = blockIdx.z;
    const int bh = b * HH + h;
    const int j = threadIdx.x;
    const float* kT = g_kT + bh * FF * NN;

    unsigned long long kreg[32];
    #pragma unroll
    for (int p = 0; p < 32; p++) {
        float lo = kT[(2 * p) * NN + j];
        float hi = kT[(2 * p + 1) * NN + j];
        asm("mov.b64 %0,{%1,%2};" : "=l"(kreg[p]) : "f"(lo), "f"(hi));
    }

    __shared__ __align__(16) float qs[16][64];
    __shared__ float red[16][16];  // [il][wid]
    __shared__ float bmax[16];
    __shared__ float bsumr[16];
    const int iBase = chunk * 16;
    const float* qp = g_q + (bh * NN + iBase) * FF;
    for (int t = threadIdx.x; t < 16 * 64; t += 512) ((float*)qs)[t] = qp[t];
    __syncthreads();

    const int wid = threadIdx.x >> 5, lane = threadIdx.x & 31;

    // --- phase 1: all 16 scores, no syncs ---
    float s[16];
    #pragma unroll
    for (int il = 0; il < 16; il++) {
        const double2* q2 = (const double2*)(&qs[il][0]);
        unsigned long long aA = 0ull, aB = 0ull;
        #pragma unroll
        for (int p = 0; p < 16; p++) {
            double2 qq = q2[p];
            unsigned long long qa = __double_as_longlong(qq.x);
            unsigned long long qb = __double_as_longlong(qq.y);
            asm("fma.rn.f32x2 %0,%1,%2,%0;" : "+l"(aA) : "l"(qa), "l"(kreg[2 * p]));
            asm("fma.rn.f32x2 %0,%1,%2,%0;" : "+l"(aB) : "l"(qb), "l"(kreg[2 * p + 1]));
        }
        float a0, a1, b0, b1;
        asm("mov.b64 {%0,%1},%2;" : "=f"(a0), "=f"(a1) : "l"(aA));
        asm("mov.b64 {%0,%1},%2;" : "=f"(b0), "=f"(b1) : "l"(aB));
        s[il] = ((a0 + b0) + (a1 + b1)) * 0.125f;  // / sqrt(64)
    }

    // --- phase 2: batched block-max over all 16 rows (2 syncs) ---
    #pragma unroll
    for (int il = 0; il < 16; il++) {
        float m = s[il];
        #pragma unroll
        for (int o = 16; o; o >>= 1) m = fmaxf(m, __shfl_xor_sync(0xffffffffu, m, o));
        if (lane == 0) red[il][wid] = m;
    }
    __syncthreads();
    {   // warp w reduces row w
        float v = (lane < 16) ? red[wid][lane] : -CUDART_INF_F;
        #pragma unroll
        for (int o = 8; o; o >>= 1) v = fmaxf(v, __shfl_xor_sync(0xffffffffu, v, o));
        if (lane == 0) bmax[wid] = v;
    }
    __syncthreads();

    // --- phase 3: exp + batched block-sum (2 syncs) ---
    #pragma unroll
    for (int il = 0; il < 16; il++) {
        s[il] = __expf(s[il] - bmax[il]);
        float t = s[il];
        #pragma unroll
        for (int o = 16; o; o >>= 1) t += __shfl_xor_sync(0xffffffffu, t, o);
        if (lane == 0) red[il][wid] = t;
    }
    __syncthreads();
    {
        float v = (lane < 16) ? red[wid][lane] : 0.f;
        #pragma unroll
        for (int o = 8; o; o >>= 1) v += __shfl_xor_sync(0xffffffffu, v, o);
        if (lane == 0) bsumr[wid] = 1.0f / v;
    }
    __syncthreads();

    // --- phase 4: T partial ---
    float acc = 0.f;
    #pragma unroll
    for (int il = 0; il < 16; il++)
        acc += g_nor[(iBase + il) * NN + j] * (s[il] * bsumr[il]);
    g_Tpart[chunk * (BB * HH * NN) + bh * NN + j] = acc;
}

// ---------------- K3b: reduce T partials + column sums c ----------------
// grid 17 blocks of 512 threads: 0..15 -> g_T, 16 -> g_c.
__global__ void k_red() {
    if (blockIdx.x < 16) {
        int v = blockIdx.x * 512 + threadIdx.x;  // 0..8191
        float s = 0.f;
        #pragma unroll
        for (int ch = 0; ch < NCHUNK; ch++) s += g_Tpart[ch * (BB * HH * NN) + v];
        g_T[v] = s;
    } else {
        int j = threadIdx.x;
        float s = 0.f;
        #pragma unroll
        for (int p = 0; p < 32; p++) s += g_cpart[p * NN + j];
        g_c[j] = s;
    }
}

// ---------------- K4a: S and sx ----------------
__global__ void k_sx(const float* __restrict__ x,
                     const float* __restrict__ Wlin,
                     const float* __restrict__ blin) {
    int idx = blockIdx.x * 256 + threadIdx.x;  // over B*N*F = 131072
    int f = idx & 63, j = (idx >> 6) & 511, b = idx >> 15;
    float s = g_c[j] * blin[f];
    #pragma unroll
    for (int h = 0; h < HH; h++) s += g_T[(b * HH + h) * NN + j] * Wlin[h * FF + f];
    g_sx[idx] = x[idx] * s;
}

// ---------------- K4b: out = relu((noradj @ sx) @ Wfc + bfc) ----------------
// grid (32, B), 1024 threads = 16 i-rows x 64 f. j tiled by 32 (16 iters).
__global__ __launch_bounds__(1024) void k_out(const float* __restrict__ Wfc,
                                              const float* __restrict__ bfc,
                                              float* __restrict__ out) {
    const int iBase = blockIdx.x * 16;
    const int b = blockIdx.y;
    const int il = threadIdx.x >> 6, f = threadIdx.x & 63;

    __shared__ float sxs[32][64];   // 8 KB
    __shared__ float nrs[32][17];   // padded: stores nor[iBase+ii][j0+jj] at nrs[jj][ii]
    __shared__ float tmp[16][65];

    float acc = 0.f;
    for (int j0 = 0; j0 < NN; j0 += 32) {
        ((float*)sxs)[threadIdx.x]        = g_sx[(b * NN + j0) * FF + threadIdx.x];
        ((float*)sxs)[threadIdx.x + 1024] = g_sx[(b * NN + j0) * FF + threadIdx.x + 1024];
        if (threadIdx.x < 512) {
            int ii = threadIdx.x >> 5, jj = threadIdx.x & 31;
            nrs[jj][ii] = g_nor[(iBase + ii) * NN + j0 + jj];   // coalesced over jj
        }
        __syncthreads();
        #pragma unroll
        for (int jj = 0; jj < 32; jj++) acc += nrs[jj][il] * sxs[jj][f];
        __syncthreads();
    }

    tmp[il][f] = acc;
    __syncthreads();
    float o = bfc[f];
    #pragma unroll
    for (int ff = 0; ff < 64; ff++) o += tmp[il][ff] * Wfc[ff * 64 + f];
    out[((b * NN) + iBase + il) * FF + f] = fmaxf(o, 0.f);
}

// ---------------- launch ----------------
extern "C" void kernel_launch(void* const* d_in, const int* in_sizes, int n_in,
                              void* d_out, int out_size) {
    const float* x    = (const float*)d_in[0];
    const float* adj  = (const float*)d_in[1];
    const float* Wq   = (const float*)d_in[2];
    const float* bq   = (const float*)d_in[3];
    const float* Wk   = (const float*)d_in[4];
    const float* bk   = (const float*)d_in[5];
    const float* Wlin = (const float*)d_in[6];
    const float* blin = (const float*)d_in[7];
    const float* Wfc  = (const float*)d_in[8];
    const float* bfc  = (const float*)d_in[9];
    float* out = (float*)d_out;

    k_deg<<<NN, 256>>>(adj);
    k_nor<<<NN, NN>>>(adj);
    k_csum<<<32, NN>>>();
    k_proj<<<dim3(64, 2), 256>>>(x, Wq, bq, Wk, bk);
    k_attn<<<dim3(NCHUNK, HH, BB), 512>>>();
    k_red<<<17, 512>>>();
    k_sx<<<512, 256>>>(x, Wlin, blin);
    k_out<<<dim3(32, BB), 1024>>>(Wfc, bfc, out);
}

// round 3
// speedup vs baseline: 1.7762x; 1.1596x over previous
#include <cuda_runtime.h>
#include <math_constants.h>

#define NN 512
#define BB 4
#define HH 4
#define FF 64
#define NCHUNK 32   // i-chunks per (b,h) in attention, 16 rows each

// ---------------- scratch (device globals; no allocation) ----------------
__device__ float g_d[NN];                       // rsqrt degrees
__device__ float g_c[NN];                       // col sums of noradj
__device__ float g_cpart[32 * NN];              // col-sum partials
__device__ float g_nor[NN * NN];                // noradj[i][j]
__device__ float g_q[BB * HH * NN * FF];        // [bh][n][f]
__device__ float g_kT[BB * HH * FF * NN];       // [bh][f][n]
__device__ float g_Tpart[NCHUNK * BB * HH * NN];// per-chunk partials (deterministic)
__device__ float g_T[BB * HH * NN];             // reduced T[bh][j]
__device__ float g_sx[BB * NN * FF];            // x * S

// ---------------- f32x2 helpers (Blackwell packed fp32) ----------------
__device__ __forceinline__ unsigned long long f2pack(float a, float b) {
    unsigned long long r;
    asm("mov.b64 %0,{%1,%2};" : "=l"(r) : "f"(a), "f"(b));
    return r;
}
__device__ __forceinline__ void f2fma(unsigned long long& d, unsigned long long a,
                                      unsigned long long b) {
    asm("fma.rn.f32x2 %0,%1,%2,%0;" : "+l"(d) : "l"(a), "l"(b));
}
__device__ __forceinline__ void f2unpack(unsigned long long v, float& a, float& b) {
    asm("mov.b64 {%0,%1},%2;" : "=f"(a), "=f"(b) : "l"(v));
}

__device__ __forceinline__ float blockReduceSum256(float v, float* red) {
    #pragma unroll
    for (int o = 16; o; o >>= 1) v += __shfl_xor_sync(0xffffffffu, v, o);
    int wid = threadIdx.x >> 5, lane = threadIdx.x & 31;
    if (lane == 0) red[wid] = v;
    __syncthreads();
    float r = (threadIdx.x < 8) ? red[threadIdx.x] : 0.f;
    if (wid == 0) {
        #pragma unroll
        for (int o = 4; o; o >>= 1) r += __shfl_xor_sync(0xffffffffu, r, o);
    }
    return r;  // valid in thread 0
}

// ---------------- K1a: degrees ----------------
__global__ void k_deg(const float* __restrict__ adj) {
    __shared__ float red[8];
    int i = blockIdx.x;
    float s = 0.f;
    for (int j = threadIdx.x; j < NN; j += 256) s += adj[i * NN + j];
    s = blockReduceSum256(s, red);
    if (threadIdx.x == 0) g_d[i] = rsqrtf(s + 1.0f);
}

// ---------------- K1b: normalized adjacency + fused col-sum partials ------
// 32 blocks x 512 threads; block bk handles rows [16bk, 16bk+16).
__global__ __launch_bounds__(512) void k_nor(const float* __restrict__ adj) {
    const int bk = blockIdx.x;
    const int j = threadIdx.x;
    const float dj = g_d[j];
    float s = 0.f;
    #pragma unroll
    for (int r = 0; r < 16; r++) {
        int i = bk * 16 + r;
        float a = adj[i * NN + j] + (i == j ? 1.0f : 0.0f);
        float v = g_d[i] * dj * a;
        g_nor[i * NN + j] = v;
        s += v;
    }
    g_cpart[bk * NN + j] = s;
}

// ---------------- K2: q/k projections, 64x64 smem-tiled GEMM --------------
// grid (32, 8): by 0..3 -> q head by; by 4..7 -> k head by-4.
// 256 threads, thread tile 4x4.
__global__ __launch_bounds__(256) void k_proj(const float* __restrict__ x,
                                              const float* __restrict__ Wq,
                                              const float* __restrict__ bq,
                                              const float* __restrict__ Wk,
                                              const float* __restrict__ bk) {
    const int by = blockIdx.y;
    const bool isK = by >= 4;
    const float* W = isK ? Wk : Wq;
    const float* bias = isK ? bk : bq;
    const int h = isK ? by - 4 : by;
    const int c0 = h * 64;
    const int rowBase = blockIdx.x * 64;
    const int b = rowBase >> 9;
    const int bh = b * HH + h;
    const int nb = rowBase & 511;

    __shared__ float xs[64][65];
    __shared__ float ws[64][64];

    const int t = threadIdx.x;
    const int tx = t & 15, ty = t >> 4;

    #pragma unroll
    for (int i = 0; i < 4; i++) {
        int lin4 = t + i * 256;              // 0..1023
        int r = lin4 >> 4, c4 = (lin4 & 15) * 4;
        float4 v = *(const float4*)(x + rowBase * 64 + lin4 * 4);
        xs[r][c4] = v.x; xs[r][c4 + 1] = v.y; xs[r][c4 + 2] = v.z; xs[r][c4 + 3] = v.w;
        *(float4*)&ws[r][c4] = *(const float4*)(W + r * 256 + c0 + c4);
    }
    __syncthreads();

    float acc[4][4];
    #pragma unroll
    for (int i = 0; i < 4; i++)
        #pragma unroll
        for (int jj = 0; jj < 4; jj++) acc[i][jj] = 0.f;

    #pragma unroll 8
    for (int k = 0; k < 64; k++) {
        float a0 = xs[4 * ty + 0][k];
        float a1 = xs[4 * ty + 1][k];
        float a2 = xs[4 * ty + 2][k];
        float a3 = xs[4 * ty + 3][k];
        float4 bv = *(float4*)&ws[k][4 * tx];
        acc[0][0] += a0 * bv.x; acc[0][1] += a0 * bv.y; acc[0][2] += a0 * bv.z; acc[0][3] += a0 * bv.w;
        acc[1][0] += a1 * bv.x; acc[1][1] += a1 * bv.y; acc[1][2] += a1 * bv.z; acc[1][3] += a1 * bv.w;
        acc[2][0] += a2 * bv.x; acc[2][1] += a2 * bv.y; acc[2][2] += a2 * bv.z; acc[2][3] += a2 * bv.w;
        acc[3][0] += a3 * bv.x; acc[3][1] += a3 * bv.y; acc[3][2] += a3 * bv.z; acc[3][3] += a3 * bv.w;
    }

    float4 bb = *(const float4*)&bias[c0 + 4 * tx];
    #pragma unroll
    for (int rr = 0; rr < 4; rr++) {
        acc[rr][0] += bb.x; acc[rr][1] += bb.y; acc[rr][2] += bb.z; acc[rr][3] += bb.w;
    }

    if (!isK) {
        #pragma unroll
        for (int rr = 0; rr < 4; rr++) {
            int n = nb + 4 * ty + rr;
            *(float4*)&g_q[(bh * NN + n) * FF + 4 * tx] =
                make_float4(acc[rr][0], acc[rr][1], acc[rr][2], acc[rr][3]);
        }
    } else {
        __syncthreads();
        float (*trans)[64] = (float(*)[64])ws;  // reuse ws
        #pragma unroll
        for (int cc = 0; cc < 4; cc++) {
            *(float4*)&trans[4 * tx + cc][4 * ty] =
                make_float4(acc[0][cc], acc[1][cc], acc[2][cc], acc[3][cc]);
        }
        __syncthreads();
        int cpr = t >> 2;              // f offset 0..63
        int seg = (t & 3) * 16;        // 16 n's per thread
        #pragma unroll
        for (int u = 0; u < 4; u++) {
            *(float4*)&g_kT[(bh * FF + cpr) * NN + nb + seg + u * 4] =
                *(float4*)&trans[cpr][seg + u * 4];
        }
    }
}

// ---------------- K3: scores + batched softmax + noradj-weighted reduce ----
__global__ __launch_bounds__(512, 1) void k_attn() {
    const int chunk = blockIdx.x, h = blockIdx.y, b = blockIdx.z;
    const int bh = b * HH + h;
    const int j = threadIdx.x;
    const float* kT = g_kT + bh * FF * NN;

    unsigned long long kreg[32];
    #pragma unroll
    for (int p = 0; p < 32; p++) {
        float lo = kT[(2 * p) * NN + j];
        float hi = kT[(2 * p + 1) * NN + j];
        kreg[p] = f2pack(lo, hi);
    }

    __shared__ __align__(16) float qs[16][64];
    __shared__ float red[16][16];  // [il][wid]
    __shared__ float bmax[16];
    __shared__ float bsumr[16];
    const int iBase = chunk * 16;
    const float* qp = g_q + (bh * NN + iBase) * FF;
    for (int t = threadIdx.x; t < 16 * 64; t += 512) ((float*)qs)[t] = qp[t];
    __syncthreads();

    const int wid = threadIdx.x >> 5, lane = threadIdx.x & 31;

    // --- phase 1: all 16 scores, no syncs ---
    float s[16];
    #pragma unroll
    for (int il = 0; il < 16; il++) {
        const double2* q2 = (const double2*)(&qs[il][0]);
        unsigned long long aA = 0ull, aB = 0ull;
        #pragma unroll
        for (int p = 0; p < 16; p++) {
            double2 qq = q2[p];
            unsigned long long qa = __double_as_longlong(qq.x);
            unsigned long long qb = __double_as_longlong(qq.y);
            f2fma(aA, qa, kreg[2 * p]);
            f2fma(aB, qb, kreg[2 * p + 1]);
        }
        float a0, a1, b0, b1;
        f2unpack(aA, a0, a1);
        f2unpack(aB, b0, b1);
        s[il] = ((a0 + b0) + (a1 + b1)) * 0.125f;  // / sqrt(64)
    }

    // --- phase 2: batched block-max (2 syncs) ---
    #pragma unroll
    for (int il = 0; il < 16; il++) {
        float m = s[il];
        #pragma unroll
        for (int o = 16; o; o >>= 1) m = fmaxf(m, __shfl_xor_sync(0xffffffffu, m, o));
        if (lane == 0) red[il][wid] = m;
    }
    __syncthreads();
    {
        float v = (lane < 16) ? red[wid][lane] : -CUDART_INF_F;
        #pragma unroll
        for (int o = 8; o; o >>= 1) v = fmaxf(v, __shfl_xor_sync(0xffffffffu, v, o));
        if (lane == 0) bmax[wid] = v;
    }
    __syncthreads();

    // --- phase 3: exp + batched block-sum (2 syncs) ---
    #pragma unroll
    for (int il = 0; il < 16; il++) {
        s[il] = __expf(s[il] - bmax[il]);
        float t = s[il];
        #pragma unroll
        for (int o = 16; o; o >>= 1) t += __shfl_xor_sync(0xffffffffu, t, o);
        if (lane == 0) red[il][wid] = t;
    }
    __syncthreads();
    {
        float v = (lane < 16) ? red[wid][lane] : 0.f;
        #pragma unroll
        for (int o = 8; o; o >>= 1) v += __shfl_xor_sync(0xffffffffu, v, o);
        if (lane == 0) bsumr[wid] = 1.0f / v;
    }
    __syncthreads();

    // --- phase 4: T partial ---
    float acc = 0.f;
    #pragma unroll
    for (int il = 0; il < 16; il++)
        acc += g_nor[(iBase + il) * NN + j] * (s[il] * bsumr[il]);
    g_Tpart[chunk * (BB * HH * NN) + bh * NN + j] = acc;
}

// ---------------- K3b: reduce T partials + column sums c ----------------
__global__ void k_red() {
    if (blockIdx.x < 16) {
        int v = blockIdx.x * 512 + threadIdx.x;  // 0..8191
        float s = 0.f;
        #pragma unroll
        for (int ch = 0; ch < NCHUNK; ch++) s += g_Tpart[ch * (BB * HH * NN) + v];
        g_T[v] = s;
    } else {
        int j = threadIdx.x;
        float s = 0.f;
        #pragma unroll
        for (int p = 0; p < 32; p++) s += g_cpart[p * NN + j];
        g_c[j] = s;
    }
}

// ---------------- K4a: S and sx ----------------
__global__ void k_sx(const float* __restrict__ x,
                     const float* __restrict__ Wlin,
                     const float* __restrict__ blin) {
    int idx = blockIdx.x * 256 + threadIdx.x;  // over B*N*F = 131072
    int f = idx & 63, j = (idx >> 6) & 511, b = idx >> 15;
    float s = g_c[j] * blin[f];
    #pragma unroll
    for (int h = 0; h < HH; h++) s += g_T[(b * HH + h) * NN + j] * Wlin[h * FF + f];
    g_sx[idx] = x[idx] * s;
}

// ---------------- K4b: out = relu((noradj @ sx) @ Wfc + bfc), f32x2 -------
// grid (32, B), 256 threads = 16 i-rows x 16 f-quads.
__global__ __launch_bounds__(256) void k_out(const float* __restrict__ Wfc,
                                             const float* __restrict__ bfc,
                                             float* __restrict__ out) {
    const int iBase = blockIdx.x * 16;
    const int b = blockIdx.y;
    const int t = threadIdx.x;
    const int il = t >> 4, fq = t & 15;

    __shared__ float sxs[32][64];   // 8 KB
    __shared__ float nrs[32][17];
    __shared__ float wfcs[64 * 64]; // 16 KB
    __shared__ float tmp[16][68];

    #pragma unroll
    for (int i = 0; i < 4; i++) {
        int l4 = t + i * 256;
        ((float4*)wfcs)[l4] = ((const float4*)Wfc)[l4];
    }

    unsigned long long acc0 = 0ull, acc1 = 0ull;
    for (int j0 = 0; j0 < NN; j0 += 32) {
        #pragma unroll
        for (int i = 0; i < 2; i++) {
            int lin = t + i * 256;  // 0..511
            ((float4*)sxs)[lin] = *(const float4*)(g_sx + (b * NN + j0) * FF + lin * 4);
            int ii = lin >> 5, jj = lin & 31;
            nrs[jj][ii] = g_nor[(iBase + ii) * NN + j0 + jj];
        }
        __syncthreads();
        #pragma unroll
        for (int jj = 0; jj < 32; jj++) {
            float nr = nrs[jj][il];
            unsigned long long nr2 = f2pack(nr, nr);
            const unsigned long long* sp = (const unsigned long long*)&sxs[jj][4 * fq];
            f2fma(acc0, nr2, sp[0]);
            f2fma(acc1, nr2, sp[1]);
        }
        __syncthreads();
    }

    float v0, v1, v2, v3;
    f2unpack(acc0, v0, v1);
    f2unpack(acc1, v2, v3);
    tmp[il][4 * fq] = v0; tmp[il][4 * fq + 1] = v1;
    tmp[il][4 * fq + 2] = v2; tmp[il][4 * fq + 3] = v3;
    __syncthreads();

    float4 bb = *(const float4*)&bfc[4 * fq];
    unsigned long long o0 = f2pack(bb.x, bb.y);
    unsigned long long o1 = f2pack(bb.z, bb.w);
    #pragma unroll
    for (int ff = 0; ff < 64; ff++) {
        float tv = tmp[il][ff];
        unsigned long long tv2 = f2pack(tv, tv);
        const unsigned long long* wp = (const unsigned long long*)&wfcs[ff * 64 + 4 * fq];
        f2fma(o0, tv2, wp[0]);
        f2fma(o1, tv2, wp[1]);
    }
    float r0, r1, r2, r3;
    f2unpack(o0, r0, r1);
    f2unpack(o1, r2, r3);
    *(float4*)&out[((b * NN) + iBase + il) * FF + 4 * fq] =
        make_float4(fmaxf(r0, 0.f), fmaxf(r1, 0.f), fmaxf(r2, 0.f), fmaxf(r3, 0.f));
}

// ---------------- launch ----------------
extern "C" void kernel_launch(void* const* d_in, const int* in_sizes, int n_in,
                              void* d_out, int out_size) {
    const float* x    = (const float*)d_in[0];
    const float* adj  = (const float*)d_in[1];
    const float* Wq   = (const float*)d_in[2];
    const float* bq   = (const float*)d_in[3];
    const float* Wk   = (const float*)d_in[4];
    const float* bk   = (const float*)d_in[5];
    const float* Wlin = (const float*)d_in[6];
    const float* blin = (const float*)d_in[7];
    const float* Wfc  = (const float*)d_in[8];
    const float* bfc  = (const float*)d_in[9];
    float* out = (float*)d_out;

    k_deg<<<NN, 256>>>(adj);
    k_nor<<<32, 512>>>(adj);
    k_proj<<<dim3(32, 8), 256>>>(x, Wq, bq, Wk, bk);
    k_attn<<<dim3(NCHUNK, HH, BB), 512>>>();
    k_red<<<17, 512>>>();
    k_sx<<<512, 256>>>(x, Wlin, blin);
    k_out<<<dim3(32, BB), 256>>>(Wfc, bfc, out);
}

// round 4
// speedup vs baseline: 1.9194x; 1.0806x over previous
#include <cuda_runtime.h>
#include <math_constants.h>

#define NN 512
#define BB 4
#define HH 4
#define FF 64
#define NCHUNK 32   // i-chunks per (b,h) in attention, 16 rows each

// ---------------- scratch (device globals; no allocation) ----------------
__device__ float g_d[NN];                       // rsqrt degrees
__device__ float g_c[NN];                       // col sums of noradj
__device__ float g_cpart[128 * NN];             // col-sum partials
__device__ float g_nor[NN * NN];                // noradj[i][j]
__device__ float g_q[BB * HH * NN * FF];        // [bh][n][f]
__device__ float g_kT[BB * HH * FF * NN];       // [bh][f][n]
__device__ float g_Tpart[NCHUNK * BB * HH * NN];// per-chunk partials (deterministic)
__device__ float g_T[BB * HH * NN];             // reduced T[bh][j]

// ---------------- f32x2 helpers (Blackwell packed fp32) ----------------
__device__ __forceinline__ unsigned long long f2pack(float a, float b) {
    unsigned long long r;
    asm("mov.b64 %0,{%1,%2};" : "=l"(r) : "f"(a), "f"(b));
    return r;
}
__device__ __forceinline__ void f2fma(unsigned long long& d, unsigned long long a,
                                      unsigned long long b) {
    asm("fma.rn.f32x2 %0,%1,%2,%0;" : "+l"(d) : "l"(a), "l"(b));
}
__device__ __forceinline__ void f2unpack(unsigned long long v, float& a, float& b) {
    asm("mov.b64 {%0,%1},%2;" : "=f"(a), "=f"(b) : "l"(v));
}

__device__ __forceinline__ float blockReduceSum256(float v, float* red) {
    #pragma unroll
    for (int o = 16; o; o >>= 1) v += __shfl_xor_sync(0xffffffffu, v, o);
    int wid = threadIdx.x >> 5, lane = threadIdx.x & 31;
    if (lane == 0) red[wid] = v;
    __syncthreads();
    float r = (threadIdx.x < 8) ? red[threadIdx.x] : 0.f;
    if (wid == 0) {
        #pragma unroll
        for (int o = 4; o; o >>= 1) r += __shfl_xor_sync(0xffffffffu, r, o);
    }
    return r;  // valid in thread 0
}

// ---------------- K1a: degrees ----------------
__global__ void k_deg(const float* __restrict__ adj) {
    __shared__ float red[8];
    int i = blockIdx.x;
    float s = 0.f;
    for (int j = threadIdx.x; j < NN; j += 256) s += adj[i * NN + j];
    s = blockReduceSum256(s, red);
    if (threadIdx.x == 0) g_d[i] = rsqrtf(s + 1.0f);
}

// ---------------- K1b: normalized adjacency + fused col-sum partials ------
// 128 blocks x 512 threads; block bk handles rows [4bk, 4bk+4).
__global__ __launch_bounds__(512) void k_nor(const float* __restrict__ adj) {
    const int bk = blockIdx.x;
    const int j = threadIdx.x;
    const float dj = g_d[j];
    float s = 0.f;
    #pragma unroll
    for (int r = 0; r < 4; r++) {
        int i = bk * 4 + r;
        float a = adj[i * NN + j] + (i == j ? 1.0f : 0.0f);
        float v = g_d[i] * dj * a;
        g_nor[i * NN + j] = v;
        s += v;
    }
    g_cpart[bk * NN + j] = s;
}

// ---------------- K2: q/k projections, 64x64 smem-tiled GEMM --------------
__global__ __launch_bounds__(256) void k_proj(const float* __restrict__ x,
                                              const float* __restrict__ Wq,
                                              const float* __restrict__ bq,
                                              const float* __restrict__ Wk,
                                              const float* __restrict__ bk) {
    const int by = blockIdx.y;
    const bool isK = by >= 4;
    const float* W = isK ? Wk : Wq;
    const float* bias = isK ? bk : bq;
    const int h = isK ? by - 4 : by;
    const int c0 = h * 64;
    const int rowBase = blockIdx.x * 64;
    const int b = rowBase >> 9;
    const int bh = b * HH + h;
    const int nb = rowBase & 511;

    __shared__ float xs[64][65];
    __shared__ float ws[64][64];

    const int t = threadIdx.x;
    const int tx = t & 15, ty = t >> 4;

    #pragma unroll
    for (int i = 0; i < 4; i++) {
        int lin4 = t + i * 256;              // 0..1023
        int r = lin4 >> 4, c4 = (lin4 & 15) * 4;
        float4 v = *(const float4*)(x + rowBase * 64 + lin4 * 4);
        xs[r][c4] = v.x; xs[r][c4 + 1] = v.y; xs[r][c4 + 2] = v.z; xs[r][c4 + 3] = v.w;
        *(float4*)&ws[r][c4] = *(const float4*)(W + r * 256 + c0 + c4);
    }
    __syncthreads();

    float acc[4][4];
    #pragma unroll
    for (int i = 0; i < 4; i++)
        #pragma unroll
        for (int jj = 0; jj < 4; jj++) acc[i][jj] = 0.f;

    #pragma unroll 8
    for (int k = 0; k < 64; k++) {
        float a0 = xs[4 * ty + 0][k];
        float a1 = xs[4 * ty + 1][k];
        float a2 = xs[4 * ty + 2][k];
        float a3 = xs[4 * ty + 3][k];
        float4 bv = *(float4*)&ws[k][4 * tx];
        acc[0][0] += a0 * bv.x; acc[0][1] += a0 * bv.y; acc[0][2] += a0 * bv.z; acc[0][3] += a0 * bv.w;
        acc[1][0] += a1 * bv.x; acc[1][1] += a1 * bv.y; acc[1][2] += a1 * bv.z; acc[1][3] += a1 * bv.w;
        acc[2][0] += a2 * bv.x; acc[2][1] += a2 * bv.y; acc[2][2] += a2 * bv.z; acc[2][3] += a2 * bv.w;
        acc[3][0] += a3 * bv.x; acc[3][1] += a3 * bv.y; acc[3][2] += a3 * bv.z; acc[3][3] += a3 * bv.w;
    }

    float4 bb = *(const float4*)&bias[c0 + 4 * tx];
    #pragma unroll
    for (int rr = 0; rr < 4; rr++) {
        acc[rr][0] += bb.x; acc[rr][1] += bb.y; acc[rr][2] += bb.z; acc[rr][3] += bb.w;
    }

    if (!isK) {
        #pragma unroll
        for (int rr = 0; rr < 4; rr++) {
            int n = nb + 4 * ty + rr;
            *(float4*)&g_q[(bh * NN + n) * FF + 4 * tx] =
                make_float4(acc[rr][0], acc[rr][1], acc[rr][2], acc[rr][3]);
        }
    } else {
        __syncthreads();
        float (*trans)[64] = (float(*)[64])ws;  // reuse ws
        #pragma unroll
        for (int cc = 0; cc < 4; cc++) {
            *(float4*)&trans[4 * tx + cc][4 * ty] =
                make_float4(acc[0][cc], acc[1][cc], acc[2][cc], acc[3][cc]);
        }
        __syncthreads();
        int cpr = t >> 2;              // f offset 0..63
        int seg = (t & 3) * 16;        // 16 n's per thread
        #pragma unroll
        for (int u = 0; u < 4; u++) {
            *(float4*)&g_kT[(bh * FF + cpr) * NN + nb + seg + u * 4] =
                *(float4*)&trans[cpr][seg + u * 4];
        }
    }
}

// ---------------- K3: scores + softmax(no-max) + noradj-weighted reduce ---
// f-dimension split in two halves to keep only 16 packed k regs live.
__global__ __launch_bounds__(512) void k_attn() {
    const int chunk = blockIdx.x, h = blockIdx.y, b = blockIdx.z;
    const int bh = b * HH + h;
    const int j = threadIdx.x;

    __shared__ __align__(16) float qs[16][64];
    __shared__ float red[16][16];  // [il][wid]
    __shared__ float bsumr[16];
    const int iBase = chunk * 16;
    const float* qp = g_q + (bh * NN + iBase) * FF;
    for (int t = threadIdx.x; t < 16 * 64; t += 512) ((float*)qs)[t] = qp[t];
    __syncthreads();

    const int wid = threadIdx.x >> 5, lane = threadIdx.x & 31;

    // --- phase 1: all 16 scores, two f-halves ---
    float s[16];
    #pragma unroll
    for (int half = 0; half < 2; half++) {
        unsigned long long kreg[16];
        const float* kp = g_kT + bh * FF * NN + (half * 32) * NN + j;
        #pragma unroll
        for (int p = 0; p < 16; p++)
            kreg[p] = f2pack(kp[(2 * p) * NN], kp[(2 * p + 1) * NN]);
        #pragma unroll
        for (int il = 0; il < 16; il++) {
            const double2* q2 = (const double2*)(&qs[il][half * 32]);
            unsigned long long aA = 0ull, aB = 0ull;
            #pragma unroll
            for (int p = 0; p < 8; p++) {
                double2 qq = q2[p];
                f2fma(aA, __double_as_longlong(qq.x), kreg[2 * p]);
                f2fma(aB, __double_as_longlong(qq.y), kreg[2 * p + 1]);
            }
            float a0, a1, b0, b1;
            f2unpack(aA, a0, a1);
            f2unpack(aB, b0, b1);
            float part = (a0 + b0) + (a1 + b1);
            s[il] = half ? (s[il] + part) : part;
        }
    }

    // --- exp without max subtraction (scores are O(1), no overflow risk) ---
    #pragma unroll
    for (int il = 0; il < 16; il++) s[il] = __expf(s[il] * 0.125f);

    // prefetch nor for phase 4 (overlaps with reduction)
    float nr[16];
    #pragma unroll
    for (int il = 0; il < 16; il++) nr[il] = g_nor[(iBase + il) * NN + j];

    // --- batched block-sum over 512 (2 syncs) ---
    #pragma unroll
    for (int il = 0; il < 16; il++) {
        float t = s[il];
        #pragma unroll
        for (int o = 16; o; o >>= 1) t += __shfl_xor_sync(0xffffffffu, t, o);
        if (lane == 0) red[il][wid] = t;
    }
    __syncthreads();
    {
        float v = (lane < 16) ? red[wid][lane] : 0.f;
        #pragma unroll
        for (int o = 8; o; o >>= 1) v += __shfl_xor_sync(0xffffffffu, v, o);
        if (lane == 0) bsumr[wid] = 1.0f / v;
    }
    __syncthreads();

    // --- T partial ---
    float acc = 0.f;
    #pragma unroll
    for (int il = 0; il < 16; il++) acc += nr[il] * (s[il] * bsumr[il]);
    g_Tpart[chunk * (BB * HH * NN) + bh * NN + j] = acc;
}

// ---------------- K3b: reduce T partials + column sums c ----------------
__global__ void k_red() {
    if (blockIdx.x < 16) {
        int v = blockIdx.x * 512 + threadIdx.x;  // 0..8191
        float s = 0.f;
        #pragma unroll
        for (int ch = 0; ch < NCHUNK; ch++) s += g_Tpart[ch * (BB * HH * NN) + v];
        g_T[v] = s;
    } else {
        int j = threadIdx.x;
        float s = 0.f;
        #pragma unroll
        for (int p = 0; p < 128; p++) s += g_cpart[p * NN + j];
        g_c[j] = s;
    }
}

// ---------------- K4: out = relu((noradj @ (x*S)) @ Wfc + bfc), fused -----
// S computed on the fly: S[b,j,f] = c[j]*blin[f] + sum_h T[b,h,j]*Wlin[h,f].
// grid (32, B), 256 threads = 16 i-rows x 16 f-quads.
__global__ __launch_bounds__(256) void k_out(const float* __restrict__ x,
                                             const float* __restrict__ Wlin,
                                             const float* __restrict__ blin,
                                             const float* __restrict__ Wfc,
                                             const float* __restrict__ bfc,
                                             float* __restrict__ out) {
    const int iBase = blockIdx.x * 16;
    const int b = blockIdx.y;
    const int t = threadIdx.x;
    const int il = t >> 4, fq = t & 15;

    __shared__ float sxs[32][64];    // 8 KB
    __shared__ float nrs[32][17];
    __shared__ float wfcs[64 * 64];  // 16 KB
    __shared__ float tmp[16][68];
    __shared__ float Ts[HH * NN];    // 8 KB: T for this b, [h][j]
    __shared__ float cs[NN];         // 2 KB
    __shared__ float wlins[HH][64];
    __shared__ float blins[64];

    #pragma unroll
    for (int i = 0; i < 4; i++) ((float4*)wfcs)[t + i * 256] = ((const float4*)Wfc)[t + i * 256];
    #pragma unroll
    for (int i = 0; i < 2; i++) ((float4*)Ts)[t + i * 256] = ((const float4*)(g_T + b * HH * NN))[t + i * 256];
    if (t < 128) ((float4*)cs)[t] = ((const float4*)g_c)[t];
    if (t < 64)  ((float4*)wlins)[t] = ((const float4*)Wlin)[t];
    if (t < 16)  ((float4*)blins)[t] = ((const float4*)blin)[t];
    __syncthreads();

    unsigned long long acc0 = 0ull, acc1 = 0ull;
    for (int j0 = 0; j0 < NN; j0 += 32) {
        #pragma unroll
        for (int i = 0; i < 2; i++) {
            int lin = t + i * 256;  // 0..511
            // sx tile: 32 j x 64 f as 512 float4
            int jj = lin >> 4, f4 = (lin & 15) * 4;
            int jg = j0 + jj;
            float4 xv = *(const float4*)(x + ((b * NN) + jg) * FF + f4);
            float4 bl = *(const float4*)&blins[f4];
            float cj = cs[jg];
            float4 s4;
            s4.x = cj * bl.x; s4.y = cj * bl.y; s4.z = cj * bl.z; s4.w = cj * bl.w;
            #pragma unroll
            for (int hh = 0; hh < HH; hh++) {
                float tv = Ts[hh * NN + jg];
                float4 wl = *(const float4*)&wlins[hh][f4];
                s4.x += tv * wl.x; s4.y += tv * wl.y; s4.z += tv * wl.z; s4.w += tv * wl.w;
            }
            *(float4*)&sxs[jj][f4] =
                make_float4(xv.x * s4.x, xv.y * s4.y, xv.z * s4.z, xv.w * s4.w);
            // nor tile
            int ii = lin >> 5, jjn = lin & 31;
            nrs[jjn][ii] = g_nor[(iBase + ii) * NN + j0 + jjn];
        }
        __syncthreads();
        #pragma unroll
        for (int jj = 0; jj < 32; jj++) {
            float nrv = nrs[jj][il];
            unsigned long long nr2 = f2pack(nrv, nrv);
            const unsigned long long* sp = (const unsigned long long*)&sxs[jj][4 * fq];
            f2fma(acc0, nr2, sp[0]);
            f2fma(acc1, nr2, sp[1]);
        }
        __syncthreads();
    }

    float v0, v1, v2, v3;
    f2unpack(acc0, v0, v1);
    f2unpack(acc1, v2, v3);
    tmp[il][4 * fq] = v0; tmp[il][4 * fq + 1] = v1;
    tmp[il][4 * fq + 2] = v2; tmp[il][4 * fq + 3] = v3;
    __syncthreads();

    float4 bb = *(const float4*)&bfc[4 * fq];
    unsigned long long o0 = f2pack(bb.x, bb.y);
    unsigned long long o1 = f2pack(bb.z, bb.w);
    #pragma unroll
    for (int ff = 0; ff < 64; ff++) {
        float tv = tmp[il][ff];
        unsigned long long tv2 = f2pack(tv, tv);
        const unsigned long long* wp = (const unsigned long long*)&wfcs[ff * 64 + 4 * fq];
        f2fma(o0, tv2, wp[0]);
        f2fma(o1, tv2, wp[1]);
    }
    float r0, r1, r2, r3;
    f2unpack(o0, r0, r1);
    f2unpack(o1, r2, r3);
    *(float4*)&out[((b * NN) + iBase + il) * FF + 4 * fq] =
        make_float4(fmaxf(r0, 0.f), fmaxf(r1, 0.f), fmaxf(r2, 0.f), fmaxf(r3, 0.f));
}

// ---------------- launch ----------------
extern "C" void kernel_launch(void* const* d_in, const int* in_sizes, int n_in,
                              void* d_out, int out_size) {
    const float* x    = (const float*)d_in[0];
    const float* adj  = (const float*)d_in[1];
    const float* Wq   = (const float*)d_in[2];
    const float* bq   = (const float*)d_in[3];
    const float* Wk   = (const float*)d_in[4];
    const float* bk   = (const float*)d_in[5];
    const float* Wlin = (const float*)d_in[6];
    const float* blin = (const float*)d_in[7];
    const float* Wfc  = (const float*)d_in[8];
    const float* bfc  = (const float*)d_in[9];
    float* out = (float*)d_out;

    k_deg<<<NN, 256>>>(adj);
    k_nor<<<128, 512>>>(adj);
    k_proj<<<dim3(32, 8), 256>>>(x, Wq, bq, Wk, bk);
    k_attn<<<dim3(NCHUNK, HH, BB), 512>>>();
    k_red<<<17, 512>>>();
    k_out<<<dim3(32, BB), 256>>>(x, Wlin, blin, Wfc, bfc, out);
}

// round 5
// speedup vs baseline: 2.1364x; 1.1131x over previous
#include <cuda_runtime.h>
#include <math_constants.h>

#define NN 512
#define BB 4
#define HH 4
#define FF 64
#define NCHUNK 32   // i-chunks per (b,h) in attention, 16 rows each

// ---------------- scratch (device globals; no allocation) ----------------
__device__ float g_d[NN];                       // rsqrt degrees
__device__ float g_c[NN];                       // col sums of noradj
__device__ float g_cpart[128 * NN];             // col-sum partials
__device__ float g_nor[NN * NN];                // noradj[i][j]
__device__ float g_q[BB * HH * NN * FF];        // [bh][n][f]  (pre-scaled by 1/8)
__device__ float g_kT[BB * HH * FF * NN];       // [bh][f][n]
__device__ float g_Tpart[NCHUNK * BB * HH * NN];// per-chunk partials (deterministic)
__device__ float g_T[BB * HH * NN];             // reduced T[bh][j]

// ---------------- f32x2 helpers (Blackwell packed fp32) ----------------
__device__ __forceinline__ unsigned long long f2pack(float a, float b) {
    unsigned long long r;
    asm("mov.b64 %0,{%1,%2};" : "=l"(r) : "f"(a), "f"(b));
    return r;
}
__device__ __forceinline__ void f2fma(unsigned long long& d, unsigned long long a,
                                      unsigned long long b) {
    asm("fma.rn.f32x2 %0,%1,%2,%0;" : "+l"(d) : "l"(a), "l"(b));
}
__device__ __forceinline__ void f2unpack(unsigned long long v, float& a, float& b) {
    asm("mov.b64 {%0,%1},%2;" : "=f"(a), "=f"(b) : "l"(v));
}

__device__ __forceinline__ float blockReduceSum256(float v, float* red) {
    #pragma unroll
    for (int o = 16; o; o >>= 1) v += __shfl_xor_sync(0xffffffffu, v, o);
    int wid = threadIdx.x >> 5, lane = threadIdx.x & 31;
    if (lane == 0) red[wid] = v;
    __syncthreads();
    float r = (threadIdx.x < 8) ? red[threadIdx.x] : 0.f;
    if (wid == 0) {
        #pragma unroll
        for (int o = 4; o; o >>= 1) r += __shfl_xor_sync(0xffffffffu, r, o);
    }
    return r;  // valid in thread 0
}

// ---------------- K1a: degrees ----------------
__global__ void k_deg(const float* __restrict__ adj) {
    __shared__ float red[8];
    int i = blockIdx.x;
    float s = 0.f;
    for (int j = threadIdx.x; j < NN; j += 256) s += adj[i * NN + j];
    s = blockReduceSum256(s, red);
    if (threadIdx.x == 0) g_d[i] = rsqrtf(s + 1.0f);
}

// ---------------- K1b: normalized adjacency + fused col-sum partials ------
__global__ __launch_bounds__(512) void k_nor(const float* __restrict__ adj) {
    const int bk = blockIdx.x;
    const int j = threadIdx.x;
    const float dj = g_d[j];
    float s = 0.f;
    #pragma unroll
    for (int r = 0; r < 4; r++) {
        int i = bk * 4 + r;
        float a = adj[i * NN + j] + (i == j ? 1.0f : 0.0f);
        float v = g_d[i] * dj * a;
        g_nor[i * NN + j] = v;
        s += v;
    }
    g_cpart[bk * NN + j] = s;
}

// ---------------- K2: q/k projections, 64x64 smem-tiled GEMM --------------
// q output is pre-scaled by 0.125 (= 1/sqrt(F)) so k_attn skips the scale.
__global__ __launch_bounds__(256) void k_proj(const float* __restrict__ x,
                                              const float* __restrict__ Wq,
                                              const float* __restrict__ bq,
                                              const float* __restrict__ Wk,
                                              const float* __restrict__ bk) {
    const int by = blockIdx.y;
    const bool isK = by >= 4;
    const float* W = isK ? Wk : Wq;
    const float* bias = isK ? bk : bq;
    const int h = isK ? by - 4 : by;
    const int c0 = h * 64;
    const int rowBase = blockIdx.x * 64;
    const int b = rowBase >> 9;
    const int bh = b * HH + h;
    const int nb = rowBase & 511;

    __shared__ float xs[64][65];
    __shared__ float ws[64][64];

    const int t = threadIdx.x;
    const int tx = t & 15, ty = t >> 4;

    #pragma unroll
    for (int i = 0; i < 4; i++) {
        int lin4 = t + i * 256;              // 0..1023
        int r = lin4 >> 4, c4 = (lin4 & 15) * 4;
        float4 v = *(const float4*)(x + rowBase * 64 + lin4 * 4);
        xs[r][c4] = v.x; xs[r][c4 + 1] = v.y; xs[r][c4 + 2] = v.z; xs[r][c4 + 3] = v.w;
        *(float4*)&ws[r][c4] = *(const float4*)(W + r * 256 + c0 + c4);
    }
    __syncthreads();

    float acc[4][4];
    #pragma unroll
    for (int i = 0; i < 4; i++)
        #pragma unroll
        for (int jj = 0; jj < 4; jj++) acc[i][jj] = 0.f;

    #pragma unroll 8
    for (int k = 0; k < 64; k++) {
        float a0 = xs[4 * ty + 0][k];
        float a1 = xs[4 * ty + 1][k];
        float a2 = xs[4 * ty + 2][k];
        float a3 = xs[4 * ty + 3][k];
        float4 bv = *(float4*)&ws[k][4 * tx];
        acc[0][0] += a0 * bv.x; acc[0][1] += a0 * bv.y; acc[0][2] += a0 * bv.z; acc[0][3] += a0 * bv.w;
        acc[1][0] += a1 * bv.x; acc[1][1] += a1 * bv.y; acc[1][2] += a1 * bv.z; acc[1][3] += a1 * bv.w;
        acc[2][0] += a2 * bv.x; acc[2][1] += a2 * bv.y; acc[2][2] += a2 * bv.z; acc[2][3] += a2 * bv.w;
        acc[3][0] += a3 * bv.x; acc[3][1] += a3 * bv.y; acc[3][2] += a3 * bv.z; acc[3][3] += a3 * bv.w;
    }

    float4 bb = *(const float4*)&bias[c0 + 4 * tx];
    #pragma unroll
    for (int rr = 0; rr < 4; rr++) {
        acc[rr][0] += bb.x; acc[rr][1] += bb.y; acc[rr][2] += bb.z; acc[rr][3] += bb.w;
    }

    if (!isK) {
        #pragma unroll
        for (int rr = 0; rr < 4; rr++) {
            int n = nb + 4 * ty + rr;
            *(float4*)&g_q[(bh * NN + n) * FF + 4 * tx] =
                make_float4(acc[rr][0] * 0.125f, acc[rr][1] * 0.125f,
                            acc[rr][2] * 0.125f, acc[rr][3] * 0.125f);
        }
    } else {
        __syncthreads();
        float (*trans)[64] = (float(*)[64])ws;  // reuse ws
        #pragma unroll
        for (int cc = 0; cc < 4; cc++) {
            *(float4*)&trans[4 * tx + cc][4 * ty] =
                make_float4(acc[0][cc], acc[1][cc], acc[2][cc], acc[3][cc]);
        }
        __syncthreads();
        int cpr = t >> 2;              // f offset 0..63
        int seg = (t & 3) * 16;        // 16 n's per thread
        #pragma unroll
        for (int u = 0; u < 4; u++) {
            *(float4*)&g_kT[(bh * FF + cpr) * NN + nb + seg + u * 4] =
                *(float4*)&trans[cpr][seg + u * 4];
        }
    }
}

// ---------------- K3: scores + softmax(no-max) + noradj-weighted reduce ---
// 256 threads x 2 j-columns: every q LDS feeds 2 columns (LDS count halved).
__global__ __launch_bounds__(256, 2) void k_attn() {
    const int chunk = blockIdx.x, h = blockIdx.y, b = blockIdx.z;
    const int bh = b * HH + h;
    const int j0 = threadIdx.x;
    const int j1 = threadIdx.x + 256;

    __shared__ __align__(16) float qs[16][64];
    __shared__ float red[16][8];
    __shared__ float bsumr[16];
    const int iBase = chunk * 16;
    ((float4*)qs)[threadIdx.x] =
        ((const float4*)(g_q + (bh * NN + iBase) * FF))[threadIdx.x];
    __syncthreads();

    const int wid = threadIdx.x >> 5, lane = threadIdx.x & 31;

    // --- phase 1: 16 scores for each of 2 columns, two f-halves ---
    float s0[16], s1[16];
    #pragma unroll
    for (int half = 0; half < 2; half++) {
        unsigned long long ka[16], kb[16];
        const float* kp = g_kT + bh * FF * NN + (half * 32) * NN;
        #pragma unroll
        for (int p = 0; p < 16; p++) {
            ka[p] = f2pack(kp[(2 * p) * NN + j0], kp[(2 * p + 1) * NN + j0]);
            kb[p] = f2pack(kp[(2 * p) * NN + j1], kp[(2 * p + 1) * NN + j1]);
        }
        #pragma unroll
        for (int il = 0; il < 16; il++) {
            const double2* q2 = (const double2*)(&qs[il][half * 32]);
            unsigned long long aA = 0ull, aB = 0ull, bA = 0ull, bB = 0ull;
            #pragma unroll
            for (int p = 0; p < 8; p++) {
                double2 qq = q2[p];
                unsigned long long qx = __double_as_longlong(qq.x);
                unsigned long long qy = __double_as_longlong(qq.y);
                f2fma(aA, qx, ka[2 * p]);
                f2fma(aB, qy, ka[2 * p + 1]);
                f2fma(bA, qx, kb[2 * p]);
                f2fma(bB, qy, kb[2 * p + 1]);
            }
            float a0, a1, a2, a3, c0, c1, c2, c3;
            f2unpack(aA, a0, a1); f2unpack(aB, a2, a3);
            f2unpack(bA, c0, c1); f2unpack(bB, c2, c3);
            float pa = (a0 + a2) + (a1 + a3);
            float pb = (c0 + c2) + (c1 + c3);
            if (half) { s0[il] += pa; s1[il] += pb; }
            else      { s0[il] = pa;  s1[il] = pb; }
        }
    }

    // --- exp without max subtraction (q pre-scaled; scores O(1)) ---
    #pragma unroll
    for (int il = 0; il < 16; il++) {
        s0[il] = __expf(s0[il]);
        s1[il] = __expf(s1[il]);
    }

    // prefetch nor (overlaps reduction)
    float nr0[16], nr1[16];
    #pragma unroll
    for (int il = 0; il < 16; il++) {
        nr0[il] = g_nor[(iBase + il) * NN + j0];
        nr1[il] = g_nor[(iBase + il) * NN + j1];
    }

    // --- batched block-sum over 512 columns (8 warps) ---
    #pragma unroll
    for (int il = 0; il < 16; il++) {
        float t = s0[il] + s1[il];
        #pragma unroll
        for (int o = 16; o; o >>= 1) t += __shfl_xor_sync(0xffffffffu, t, o);
        if (lane == 0) red[il][wid] = t;
    }
    __syncthreads();
    if (threadIdx.x < 16) {
        float v = 0.f;
        #pragma unroll
        for (int w = 0; w < 8; w++) v += red[threadIdx.x][w];
        bsumr[threadIdx.x] = 1.0f / v;
    }
    __syncthreads();

    // --- T partials for both columns ---
    float acc0 = 0.f, acc1 = 0.f;
    #pragma unroll
    for (int il = 0; il < 16; il++) {
        float r = bsumr[il];
        acc0 += nr0[il] * (s0[il] * r);
        acc1 += nr1[il] * (s1[il] * r);
    }
    float* tp = g_Tpart + chunk * (BB * HH * NN) + bh * NN;
    tp[j0] = acc0;
    tp[j1] = acc1;
}

// ---------------- K3b: reduce T partials + column sums c ----------------
__global__ void k_red() {
    if (blockIdx.x < 16) {
        int v = blockIdx.x * 512 + threadIdx.x;  // 0..8191
        float s = 0.f;
        #pragma unroll
        for (int ch = 0; ch < NCHUNK; ch++) s += g_Tpart[ch * (BB * HH * NN) + v];
        g_T[v] = s;
    } else {
        int j = threadIdx.x;
        float s = 0.f;
        #pragma unroll
        for (int p = 0; p < 128; p++) s += g_cpart[p * NN + j];
        g_c[j] = s;
    }
}

// ---------------- K4: out = relu((noradj @ (x*S)) @ Wfc + bfc), fused -----
__global__ __launch_bounds__(256) void k_out(const float* __restrict__ x,
                                             const float* __restrict__ Wlin,
                                             const float* __restrict__ blin,
                                             const float* __restrict__ Wfc,
                                             const float* __restrict__ bfc,
                                             float* __restrict__ out) {
    const int iBase = blockIdx.x * 16;
    const int b = blockIdx.y;
    const int t = threadIdx.x;
    const int il = t >> 4, fq = t & 15;

    __shared__ float sxs[32][64];    // 8 KB
    __shared__ float nrs[32][17];
    __shared__ float wfcs[64 * 64];  // 16 KB
    __shared__ float tmp[16][68];
    __shared__ float Ts[HH * NN];    // 8 KB
    __shared__ float cs[NN];
    __shared__ float wlins[HH][64];
    __shared__ float blins[64];

    #pragma unroll
    for (int i = 0; i < 4; i++) ((float4*)wfcs)[t + i * 256] = ((const float4*)Wfc)[t + i * 256];
    #pragma unroll
    for (int i = 0; i < 2; i++) ((float4*)Ts)[t + i * 256] = ((const float4*)(g_T + b * HH * NN))[t + i * 256];
    if (t < 128) ((float4*)cs)[t] = ((const float4*)g_c)[t];
    if (t < 64)  ((float4*)wlins)[t] = ((const float4*)Wlin)[t];
    if (t < 16)  ((float4*)blins)[t] = ((const float4*)blin)[t];
    __syncthreads();

    unsigned long long acc0 = 0ull, acc1 = 0ull;
    for (int j0 = 0; j0 < NN; j0 += 32) {
        #pragma unroll
        for (int i = 0; i < 2; i++) {
            int lin = t + i * 256;  // 0..511
            int jj = lin >> 4, f4 = (lin & 15) * 4;
            int jg = j0 + jj;
            float4 xv = *(const float4*)(x + ((b * NN) + jg) * FF + f4);
            float4 bl = *(const float4*)&blins[f4];
            float cj = cs[jg];
            float4 s4;
            s4.x = cj * bl.x; s4.y = cj * bl.y; s4.z = cj * bl.z; s4.w = cj * bl.w;
            #pragma unroll
            for (int hh = 0; hh < HH; hh++) {
                float tv = Ts[hh * NN + jg];
                float4 wl = *(const float4*)&wlins[hh][f4];
                s4.x += tv * wl.x; s4.y += tv * wl.y; s4.z += tv * wl.z; s4.w += tv * wl.w;
            }
            *(float4*)&sxs[jj][f4] =
                make_float4(xv.x * s4.x, xv.y * s4.y, xv.z * s4.z, xv.w * s4.w);
            int ii = lin >> 5, jjn = lin & 31;
            nrs[jjn][ii] = g_nor[(iBase + ii) * NN + j0 + jjn];
        }
        __syncthreads();
        #pragma unroll
        for (int jj = 0; jj < 32; jj++) {
            float nrv = nrs[jj][il];
            unsigned long long nr2 = f2pack(nrv, nrv);
            const unsigned long long* sp = (const unsigned long long*)&sxs[jj][4 * fq];
            f2fma(acc0, nr2, sp[0]);
            f2fma(acc1, nr2, sp[1]);
        }
        __syncthreads();
    }

    float v0, v1, v2, v3;
    f2unpack(acc0, v0, v1);
    f2unpack(acc1, v2, v3);
    tmp[il][4 * fq] = v0; tmp[il][4 * fq + 1] = v1;
    tmp[il][4 * fq + 2] = v2; tmp[il][4 * fq + 3] = v3;
    __syncthreads();

    float4 bb = *(const float4*)&bfc[4 * fq];
    unsigned long long o0 = f2pack(bb.x, bb.y);
    unsigned long long o1 = f2pack(bb.z, bb.w);
    #pragma unroll
    for (int ff = 0; ff < 64; ff++) {
        float tv = tmp[il][ff];
        unsigned long long tv2 = f2pack(tv, tv);
        const unsigned long long* wp = (const unsigned long long*)&wfcs[ff * 64 + 4 * fq];
        f2fma(o0, tv2, wp[0]);
        f2fma(o1, tv2, wp[1]);
    }
    float r0, r1, r2, r3;
    f2unpack(o0, r0, r1);
    f2unpack(o1, r2, r3);
    *(float4*)&out[((b * NN) + iBase + il) * FF + 4 * fq] =
        make_float4(fmaxf(r0, 0.f), fmaxf(r1, 0.f), fmaxf(r2, 0.f), fmaxf(r3, 0.f));
}

// ---------------- launch ----------------
extern "C" void kernel_launch(void* const* d_in, const int* in_sizes, int n_in,
                              void* d_out, int out_size) {
    const float* x    = (const float*)d_in[0];
    const float* adj  = (const float*)d_in[1];
    const float* Wq   = (const float*)d_in[2];
    const float* bq   = (const float*)d_in[3];
    const float* Wk   = (const float*)d_in[4];
    const float* bk   = (const float*)d_in[5];
    const float* Wlin = (const float*)d_in[6];
    const float* blin = (const float*)d_in[7];
    const float* Wfc  = (const float*)d_in[8];
    const float* bfc  = (const float*)d_in[9];
    float* out = (float*)d_out;

    k_deg<<<NN, 256>>>(adj);
    k_nor<<<128, 512>>>(adj);
    k_proj<<<dim3(32, 8), 256>>>(x, Wq, bq, Wk, bk);
    k_attn<<<dim3(NCHUNK, HH, BB), 256>>>();
    k_red<<<17, 512>>>();
    k_out<<<dim3(32, BB), 256>>>(x, Wlin, blin, Wfc, bfc, out);
}

// round 7
// speedup vs baseline: 2.4754x; 1.1587x over previous
#include <cuda_runtime.h>
#include <cuda_bf16.h>
#include <math_constants.h>
#include <cstdint>

#define NN 512
#define BB 4
#define HH 4
#define FF 64
#define NCHT 8      // T-partial chunks = 8 m-tiles of 64 rows

// ---------------- scratch (device globals; no allocation) ----------------
__device__ float g_d[NN];
__device__ float g_c[NN];
__device__ float g_cpart[128 * NN];
__device__ float g_nor[NN * NN];
__device__ __nv_bfloat16 g_qh[BB * HH * NN * FF];  // q hi (pre-scaled 1/8)
__device__ __nv_bfloat16 g_ql[BB * HH * NN * FF];  // q lo
__device__ __nv_bfloat16 g_kh[BB * HH * NN * FF];  // k hi
__device__ __nv_bfloat16 g_kl[BB * HH * NN * FF];  // k lo
__device__ float g_Tpart[NCHT * BB * HH * NN];
__device__ float g_T[BB * HH * NN];

// ---------------- f32x2 helpers ----------------
__device__ __forceinline__ unsigned long long f2pack(float a, float b) {
    unsigned long long r;
    asm("mov.b64 %0,{%1,%2};" : "=l"(r) : "f"(a), "f"(b));
    return r;
}
__device__ __forceinline__ void f2fma(unsigned long long& d, unsigned long long a,
                                      unsigned long long b) {
    asm("fma.rn.f32x2 %0,%1,%2,%0;" : "+l"(d) : "l"(a), "l"(b));
}
__device__ __forceinline__ void f2unpack(unsigned long long v, float& a, float& b) {
    asm("mov.b64 {%0,%1},%2;" : "=f"(a), "=f"(b) : "l"(v));
}

// ---------------- HMMA m16n8k16 bf16 -> f32 (baseline PTX, sm_80+) -------
__device__ __forceinline__ void mma16816(float d[4], const uint32_t a[4],
                                         const uint32_t b[2]) {
    asm volatile(
        "mma.sync.aligned.m16n8k16.row.col.f32.bf16.bf16.f32 "
        "{%0,%1,%2,%3}, {%4,%5,%6,%7}, {%8,%9}, {%0,%1,%2,%3};"
        : "+f"(d[0]), "+f"(d[1]), "+f"(d[2]), "+f"(d[3])
        : "r"(a[0]), "r"(a[1]), "r"(a[2]), "r"(a[3]), "r"(b[0]), "r"(b[1]));
}

__device__ __forceinline__ float blockReduceSum256(float v, float* red) {
    #pragma unroll
    for (int o = 16; o; o >>= 1) v += __shfl_xor_sync(0xffffffffu, v, o);
    int wid = threadIdx.x >> 5, lane = threadIdx.x & 31;
    if (lane == 0) red[wid] = v;
    __syncthreads();
    float r = (threadIdx.x < 8) ? red[threadIdx.x] : 0.f;
    if (wid == 0) {
        #pragma unroll
        for (int o = 4; o; o >>= 1) r += __shfl_xor_sync(0xffffffffu, r, o);
    }
    return r;
}

// ---------------- K1a: degrees ----------------
__global__ void k_deg(const float* __restrict__ adj) {
    __shared__ float red[8];
    int i = blockIdx.x;
    float s = 0.f;
    for (int j = threadIdx.x; j < NN; j += 256) s += adj[i * NN + j];
    s = blockReduceSum256(s, red);
    if (threadIdx.x == 0) g_d[i] = rsqrtf(s + 1.0f);
}

// ---------------- K1b: normalized adjacency + col-sum partials ----------
__global__ __launch_bounds__(512) void k_nor(const float* __restrict__ adj) {
    const int bk = blockIdx.x;
    const int j = threadIdx.x;
    const float dj = g_d[j];
    float s = 0.f;
    #pragma unroll
    for (int r = 0; r < 4; r++) {
        int i = bk * 4 + r;
        float a = adj[i * NN + j] + (i == j ? 1.0f : 0.0f);
        float v = g_d[i] * dj * a;
        g_nor[i * NN + j] = v;
        s += v;
    }
    g_cpart[bk * NN + j] = s;
}

// ---------------- K2: q/k projections -> bf16 hi/lo ---------------------
__global__ __launch_bounds__(256) void k_proj(const float* __restrict__ x,
                                              const float* __restrict__ Wq,
                                              const float* __restrict__ bq,
                                              const float* __restrict__ Wk,
                                              const float* __restrict__ bk) {
    const int by = blockIdx.y;
    const bool isK = by >= 4;
    const float* W = isK ? Wk : Wq;
    const float* bias = isK ? bk : bq;
    const int h = isK ? by - 4 : by;
    const int c0 = h * 64;
    const int rowBase = blockIdx.x * 64;
    const int b = rowBase >> 9;
    const int bh = b * HH + h;
    const int nb = rowBase & 511;

    __shared__ float xs[64][65];
    __shared__ float ws[64][64];

    const int t = threadIdx.x;
    const int tx = t & 15, ty = t >> 4;

    #pragma unroll
    for (int i = 0; i < 4; i++) {
        int lin4 = t + i * 256;
        int r = lin4 >> 4, c4 = (lin4 & 15) * 4;
        float4 v = *(const float4*)(x + rowBase * 64 + lin4 * 4);
        xs[r][c4] = v.x; xs[r][c4 + 1] = v.y; xs[r][c4 + 2] = v.z; xs[r][c4 + 3] = v.w;
        *(float4*)&ws[r][c4] = *(const float4*)(W + r * 256 + c0 + c4);
    }
    __syncthreads();

    float acc[4][4];
    #pragma unroll
    for (int i = 0; i < 4; i++)
        #pragma unroll
        for (int jj = 0; jj < 4; jj++) acc[i][jj] = 0.f;

    #pragma unroll 8
    for (int k = 0; k < 64; k++) {
        float a0 = xs[4 * ty + 0][k];
        float a1 = xs[4 * ty + 1][k];
        float a2 = xs[4 * ty + 2][k];
        float a3 = xs[4 * ty + 3][k];
        float4 bv = *(float4*)&ws[k][4 * tx];
        acc[0][0] += a0 * bv.x; acc[0][1] += a0 * bv.y; acc[0][2] += a0 * bv.z; acc[0][3] += a0 * bv.w;
        acc[1][0] += a1 * bv.x; acc[1][1] += a1 * bv.y; acc[1][2] += a1 * bv.z; acc[1][3] += a1 * bv.w;
        acc[2][0] += a2 * bv.x; acc[2][1] += a2 * bv.y; acc[2][2] += a2 * bv.z; acc[2][3] += a2 * bv.w;
        acc[3][0] += a3 * bv.x; acc[3][1] += a3 * bv.y; acc[3][2] += a3 * bv.z; acc[3][3] += a3 * bv.w;
    }

    float4 bb = *(const float4*)&bias[c0 + 4 * tx];
    const float sc = isK ? 1.0f : 0.125f;   // fold 1/sqrt(F) into q
    __nv_bfloat16* dh = isK ? g_kh : g_qh;
    __nv_bfloat16* dl = isK ? g_kl : g_ql;
    #pragma unroll
    for (int rr = 0; rr < 4; rr++) {
        int n = nb + 4 * ty + rr;
        size_t o = (size_t)(bh * NN + n) * FF + 4 * tx;
        float v0 = (acc[rr][0] + bb.x) * sc;
        float v1 = (acc[rr][1] + bb.y) * sc;
        float v2 = (acc[rr][2] + bb.z) * sc;
        float v3 = (acc[rr][3] + bb.w) * sc;
        __nv_bfloat16 h0 = __float2bfloat16(v0), h1 = __float2bfloat16(v1);
        __nv_bfloat16 h2 = __float2bfloat16(v2), h3 = __float2bfloat16(v3);
        *(__nv_bfloat162*)&dh[o]     = __halves2bfloat162(h0, h1);
        *(__nv_bfloat162*)&dh[o + 2] = __halves2bfloat162(h2, h3);
        *(__nv_bfloat162*)&dl[o] = __halves2bfloat162(
            __float2bfloat16(v0 - __bfloat162float(h0)),
            __float2bfloat16(v1 - __bfloat162float(h1)));
        *(__nv_bfloat162*)&dl[o + 2] = __halves2bfloat162(
            __float2bfloat16(v2 - __bfloat162float(h2)),
            __float2bfloat16(v3 - __bfloat162float(h3)));
    }
}

// ---------------- K3: HMMA scores + softmax + noradj reduce --------------
// grid (8 mtiles, H, B) = 128 blocks, 256 threads.
// Smem: qh/ql 64x72 bf16, kh/kl 256x72 bf16 (per col-half), exp fp32 64x520.
#define QS 4608        // 64*72 elems
#define KS 18432       // 256*72 elems
#define ATTN_DSM 225280
__global__ __launch_bounds__(256, 1) void k_attn_mma() {
    extern __shared__ __align__(16) char dsm[];
    __nv_bfloat16* qh_s = (__nv_bfloat16*)dsm;
    __nv_bfloat16* ql_s = qh_s + QS;
    __nv_bfloat16* kh_s = qh_s + 2 * QS;
    __nv_bfloat16* kl_s = kh_s + KS;
    float* expb = (float*)(dsm + 92160);   // 64 x 520 fp32

    __shared__ float rsum[2][64];
    __shared__ float rinv[64];

    const int mtile = blockIdx.x, h = blockIdx.y, b = blockIdx.z;
    const int bh = b * HH + h;
    const int iBase = mtile * 64;
    const int tid = threadIdx.x;
    const int w = tid >> 5, lane = tid & 31;
    const int mrow = (w >> 1) * 16;     // warp's 16-row strip
    const int cs = w & 1;               // col strip (128 cols)
    const int r = lane >> 2, c = lane & 3;

    // --- load q (hi/lo) into smem ---
    {
        const uint4* sh = (const uint4*)(g_qh + (size_t)(bh * NN + iBase) * FF);
        const uint4* sl = (const uint4*)(g_ql + (size_t)(bh * NN + iBase) * FF);
        #pragma unroll
        for (int i = 0; i < 2; i++) {
            int idx = tid + i * 256;          // 0..511
            int row = idx >> 3, c8 = idx & 7;
            *(uint4*)&qh_s[row * 72 + c8 * 8] = sh[idx];
            *(uint4*)&ql_s[row * 72 + c8 * 8] = sl[idx];
        }
    }

    uint32_t qhA[4][4], qlA[4][4];
    float rs0 = 0.f, rs1 = 0.f;

    for (int half = 0; half < 2; half++) {
        __syncthreads();   // prev-half k reads done (and q stores visible)
        // --- load k half (hi/lo) ---
        {
            const uint4* sh = (const uint4*)(g_kh + (size_t)(bh * NN + half * 256) * FF);
            const uint4* sl = (const uint4*)(g_kl + (size_t)(bh * NN + half * 256) * FF);
            #pragma unroll
            for (int i = 0; i < 8; i++) {
                int idx = tid + i * 256;      // 0..2047
                int row = idx >> 3, c8 = idx & 7;
                *(uint4*)&kh_s[row * 72 + c8 * 8] = sh[idx];
                *(uint4*)&kl_s[row * 72 + c8 * 8] = sl[idx];
            }
        }
        __syncthreads();

        if (half == 0) {
            #pragma unroll
            for (int kt = 0; kt < 4; kt++) {
                int col = kt * 16 + 2 * c;
                qhA[kt][0] = *(const uint32_t*)&qh_s[(mrow + r) * 72 + col];
                qhA[kt][1] = *(const uint32_t*)&qh_s[(mrow + r + 8) * 72 + col];
                qhA[kt][2] = *(const uint32_t*)&qh_s[(mrow + r) * 72 + col + 8];
                qhA[kt][3] = *(const uint32_t*)&qh_s[(mrow + r + 8) * 72 + col + 8];
                qlA[kt][0] = *(const uint32_t*)&ql_s[(mrow + r) * 72 + col];
                qlA[kt][1] = *(const uint32_t*)&ql_s[(mrow + r + 8) * 72 + col];
                qlA[kt][2] = *(const uint32_t*)&ql_s[(mrow + r) * 72 + col + 8];
                qlA[kt][3] = *(const uint32_t*)&ql_s[(mrow + r + 8) * 72 + col + 8];
            }
        }

        #pragma unroll 2
        for (int nt = 0; nt < 16; nt++) {
            const int jloc = cs * 128 + nt * 8 + r;    // local k row for B frag
            uint32_t khB[4][2], klB[4][2];
            #pragma unroll
            for (int kt = 0; kt < 4; kt++) {
                int col = kt * 16 + 2 * c;
                khB[kt][0] = *(const uint32_t*)&kh_s[jloc * 72 + col];
                khB[kt][1] = *(const uint32_t*)&kh_s[jloc * 72 + col + 8];
                klB[kt][0] = *(const uint32_t*)&kl_s[jloc * 72 + col];
                klB[kt][1] = *(const uint32_t*)&kl_s[jloc * 72 + col + 8];
            }
            float d[4] = {0.f, 0.f, 0.f, 0.f};
            #pragma unroll
            for (int kt = 0; kt < 4; kt++) mma16816(d, qhA[kt], khB[kt]);
            #pragma unroll
            for (int kt = 0; kt < 4; kt++) mma16816(d, qhA[kt], klB[kt]);
            #pragma unroll
            for (int kt = 0; kt < 4; kt++) mma16816(d, qlA[kt], khB[kt]);

            float e0 = __expf(d[0]), e1 = __expf(d[1]);
            float e2 = __expf(d[2]), e3 = __expf(d[3]);
            rs0 += e0 + e1;
            rs1 += e2 + e3;
            int gcol = half * 256 + cs * 128 + nt * 8 + 2 * c;
            *(float2*)&expb[(mrow + r) * 520 + gcol]     = make_float2(e0, e1);
            *(float2*)&expb[(mrow + r + 8) * 520 + gcol] = make_float2(e2, e3);
        }
    }

    // --- rowsums: reduce over quad, combine col strips ---
    rs0 += __shfl_xor_sync(0xffffffffu, rs0, 1);
    rs0 += __shfl_xor_sync(0xffffffffu, rs0, 2);
    rs1 += __shfl_xor_sync(0xffffffffu, rs1, 1);
    rs1 += __shfl_xor_sync(0xffffffffu, rs1, 2);
    if ((lane & 3) == 0) {
        rsum[cs][mrow + r] = rs0;
        rsum[cs][mrow + r + 8] = rs1;
    }
    __syncthreads();
    if (tid < 64) rinv[tid] = 1.0f / (rsum[0][tid] + rsum[1][tid]);
    __syncthreads();

    // --- T partials: cols tid and tid+256, deterministic ---
    {
        const float* np = g_nor + (size_t)iBase * NN;
        float a0 = 0.f, a1 = 0.f;
        #pragma unroll 4
        for (int i = 0; i < 64; i++) {
            float ri = rinv[i];
            a0 += np[i * NN + tid]       * (expb[i * 520 + tid] * ri);
            a1 += np[i * NN + tid + 256] * (expb[i * 520 + tid + 256] * ri);
        }
        float* tp = g_Tpart + mtile * (BB * HH * NN) + bh * NN;
        tp[tid] = a0;
        tp[tid + 256] = a1;
    }
}

// ---------------- K3b: reduce T partials + column sums c ----------------
__global__ void k_red() {
    if (blockIdx.x < 16) {
        int v = blockIdx.x * 512 + threadIdx.x;
        float s = 0.f;
        #pragma unroll
        for (int ch = 0; ch < NCHT; ch++) s += g_Tpart[ch * (BB * HH * NN) + v];
        g_T[v] = s;
    } else {
        int j = threadIdx.x;
        float s = 0.f;
        #pragma unroll
        for (int p = 0; p < 128; p++) s += g_cpart[p * NN + j];
        g_c[j] = s;
    }
}

// ---------------- K4: out = relu((noradj @ (x*S)) @ Wfc + bfc), fused ----
__global__ __launch_bounds__(256) void k_out(const float* __restrict__ x,
                                             const float* __restrict__ Wlin,
                                             const float* __restrict__ blin,
                                             const float* __restrict__ Wfc,
                                             const float* __restrict__ bfc,
                                             float* __restrict__ out) {
    const int iBase = blockIdx.x * 16;
    const int b = blockIdx.y;
    const int t = threadIdx.x;
    const int il = t >> 4, fq = t & 15;

    __shared__ float sxs[32][64];
    __shared__ float nrs[32][17];
    __shared__ float wfcs[64 * 64];
    __shared__ float tmp[16][68];
    __shared__ float Ts[HH * NN];
    __shared__ float cs[NN];
    __shared__ float wlins[HH][64];
    __shared__ float blins[64];

    #pragma unroll
    for (int i = 0; i < 4; i++) ((float4*)wfcs)[t + i * 256] = ((const float4*)Wfc)[t + i * 256];
    #pragma unroll
    for (int i = 0; i < 2; i++) ((float4*)Ts)[t + i * 256] = ((const float4*)(g_T + b * HH * NN))[t + i * 256];
    if (t < 128) ((float4*)cs)[t] = ((const float4*)g_c)[t];
    if (t < 64)  ((float4*)wlins)[t] = ((const float4*)Wlin)[t];
    if (t < 16)  ((float4*)blins)[t] = ((const float4*)blin)[t];
    __syncthreads();

    unsigned long long acc0 = 0ull, acc1 = 0ull;
    for (int j0 = 0; j0 < NN; j0 += 32) {
        #pragma unroll
        for (int i = 0; i < 2; i++) {
            int lin = t + i * 256;
            int jj = lin >> 4, f4 = (lin & 15) * 4;
            int jg = j0 + jj;
            float4 xv = *(const float4*)(x + ((b * NN) + jg) * FF + f4);
            float4 bl = *(const float4*)&blins[f4];
            float cj = cs[jg];
            float4 s4;
            s4.x = cj * bl.x; s4.y = cj * bl.y; s4.z = cj * bl.z; s4.w = cj * bl.w;
            #pragma unroll
            for (int hh = 0; hh < HH; hh++) {
                float tv = Ts[hh * NN + jg];
                float4 wl = *(const float4*)&wlins[hh][f4];
                s4.x += tv * wl.x; s4.y += tv * wl.y; s4.z += tv * wl.z; s4.w += tv * wl.w;
            }
            *(float4*)&sxs[jj][f4] =
                make_float4(xv.x * s4.x, xv.y * s4.y, xv.z * s4.z, xv.w * s4.w);
            int ii = lin >> 5, jjn = lin & 31;
            nrs[jjn][ii] = g_nor[(iBase + ii) * NN + j0 + jjn];
        }
        __syncthreads();
        #pragma unroll
        for (int jj = 0; jj < 32; jj++) {
            float nrv = nrs[jj][il];
            unsigned long long nr2 = f2pack(nrv, nrv);
            const unsigned long long* sp = (const unsigned long long*)&sxs[jj][4 * fq];
            f2fma(acc0, nr2, sp[0]);
            f2fma(acc1, nr2, sp[1]);
        }
        __syncthreads();
    }

    float v0, v1, v2, v3;
    f2unpack(acc0, v0, v1);
    f2unpack(acc1, v2, v3);
    tmp[il][4 * fq] = v0; tmp[il][4 * fq + 1] = v1;
    tmp[il][4 * fq + 2] = v2; tmp[il][4 * fq + 3] = v3;
    __syncthreads();

    float4 bb = *(const float4*)&bfc[4 * fq];
    unsigned long long o0 = f2pack(bb.x, bb.y);
    unsigned long long o1 = f2pack(bb.z, bb.w);
    #pragma unroll
    for (int ff = 0; ff < 64; ff++) {
        float tv = tmp[il][ff];
        unsigned long long tv2 = f2pack(tv, tv);
        const unsigned long long* wp = (const unsigned long long*)&wfcs[ff * 64 + 4 * fq];
        f2fma(o0, tv2, wp[0]);
        f2fma(o1, tv2, wp[1]);
    }
    float r0, r1, r2, r3;
    f2unpack(o0, r0, r1);
    f2unpack(o1, r2, r3);
    *(float4*)&out[((b * NN) + iBase + il) * FF + 4 * fq] =
        make_float4(fmaxf(r0, 0.f), fmaxf(r1, 0.f), fmaxf(r2, 0.f), fmaxf(r3, 0.f));
}

// ---------------- launch ----------------
extern "C" void kernel_launch(void* const* d_in, const int* in_sizes, int n_in,
                              void* d_out, int out_size) {
    const float* x    = (const float*)d_in[0];
    const float* adj  = (const float*)d_in[1];
    const float* Wq   = (const float*)d_in[2];
    const float* bq   = (const float*)d_in[3];
    const float* Wk   = (const float*)d_in[4];
    const float* bk   = (const float*)d_in[5];
    const float* Wlin = (const float*)d_in[6];
    const float* blin = (const float*)d_in[7];
    const float* Wfc  = (const float*)d_in[8];
    const float* bfc  = (const float*)d_in[9];
    float* out = (float*)d_out;

    static int attr_set = 0;
    if (!attr_set) {
        cudaFuncSetAttribute(k_attn_mma,
                             cudaFuncAttributeMaxDynamicSharedMemorySize, ATTN_DSM);
        attr_set = 1;
    }

    k_deg<<<NN, 256>>>(adj);
    k_nor<<<128, 512>>>(adj);
    k_proj<<<dim3(32, 8), 256>>>(x, Wq, bq, Wk, bk);
    k_attn_mma<<<dim3(8, HH, BB), 256, ATTN_DSM>>>();
    k_red<<<17, 512>>>();
    k_out<<<dim3(32, BB), 256>>>(x, Wlin, blin, Wfc, bfc, out);
}

// round 8
// speedup vs baseline: 2.5728x; 1.0394x over previous
#include <cuda_runtime.h>
#include <cuda_bf16.h>
#include <math_constants.h>
#include <cstdint>

#define NN 512
#define BB 4
#define HH 4
#define FF 64
#define NCHT 8      // T-partial chunks = 8 m-tiles of 64 rows

// ---------------- scratch (device globals; no allocation) ----------------
__device__ float g_d[NN];
__device__ float g_c[NN];
__device__ float g_cpart[128 * NN];
__device__ float g_nor[NN * NN];
__device__ __nv_bfloat16 g_qh[BB * HH * NN * FF];  // q hi (pre-scaled 1/8)
__device__ __nv_bfloat16 g_ql[BB * HH * NN * FF];  // q lo
__device__ __nv_bfloat16 g_kh[BB * HH * NN * FF];  // k hi
__device__ __nv_bfloat16 g_kl[BB * HH * NN * FF];  // k lo
__device__ float g_Tpart[NCHT * BB * HH * NN];
__device__ float g_T[BB * HH * NN];

// ---------------- f32x2 helpers ----------------
__device__ __forceinline__ unsigned long long f2pack(float a, float b) {
    unsigned long long r;
    asm("mov.b64 %0,{%1,%2};" : "=l"(r) : "f"(a), "f"(b));
    return r;
}
__device__ __forceinline__ void f2fma(unsigned long long& d, unsigned long long a,
                                      unsigned long long b) {
    asm("fma.rn.f32x2 %0,%1,%2,%0;" : "+l"(d) : "l"(a), "l"(b));
}
__device__ __forceinline__ void f2unpack(unsigned long long v, float& a, float& b) {
    asm("mov.b64 {%0,%1},%2;" : "=f"(a), "=f"(b) : "l"(v));
}

// ---------------- HMMA m16n8k16 bf16 -> f32 ----------------
__device__ __forceinline__ void mma16816(float d[4], const uint32_t a[4],
                                         const uint32_t b[2]) {
    asm volatile(
        "mma.sync.aligned.m16n8k16.row.col.f32.bf16.bf16.f32 "
        "{%0,%1,%2,%3}, {%4,%5,%6,%7}, {%8,%9}, {%0,%1,%2,%3};"
        : "+f"(d[0]), "+f"(d[1]), "+f"(d[2]), "+f"(d[3])
        : "r"(a[0]), "r"(a[1]), "r"(a[2]), "r"(a[3]), "r"(b[0]), "r"(b[1]));
}

__device__ __forceinline__ float blockReduceSum256(float v, float* red) {
    #pragma unroll
    for (int o = 16; o; o >>= 1) v += __shfl_xor_sync(0xffffffffu, v, o);
    int wid = threadIdx.x >> 5, lane = threadIdx.x & 31;
    if (lane == 0) red[wid] = v;
    __syncthreads();
    float r = (threadIdx.x < 8) ? red[threadIdx.x] : 0.f;
    if (wid == 0) {
        #pragma unroll
        for (int o = 4; o; o >>= 1) r += __shfl_xor_sync(0xffffffffu, r, o);
    }
    return r;
}

// ---------------- K1a: degrees ----------------
__global__ void k_deg(const float* __restrict__ adj) {
    __shared__ float red[8];
    int i = blockIdx.x;
    float s = 0.f;
    for (int j = threadIdx.x; j < NN; j += 256) s += adj[i * NN + j];
    s = blockReduceSum256(s, red);
    if (threadIdx.x == 0) g_d[i] = rsqrtf(s + 1.0f);
}

// ---------------- K1b: normalized adjacency + col-sum partials ----------
__global__ __launch_bounds__(512) void k_nor(const float* __restrict__ adj) {
    const int bk = blockIdx.x;
    const int j = threadIdx.x;
    const float dj = g_d[j];
    float s = 0.f;
    #pragma unroll
    for (int r = 0; r < 4; r++) {
        int i = bk * 4 + r;
        float a = adj[i * NN + j] + (i == j ? 1.0f : 0.0f);
        float v = g_d[i] * dj * a;
        g_nor[i * NN + j] = v;
        s += v;
    }
    g_cpart[bk * NN + j] = s;
}

// ---------------- K2: q/k projections -> bf16 hi/lo ---------------------
__global__ __launch_bounds__(256) void k_proj(const float* __restrict__ x,
                                              const float* __restrict__ Wq,
                                              const float* __restrict__ bq,
                                              const float* __restrict__ Wk,
                                              const float* __restrict__ bk) {
    const int by = blockIdx.y;
    const bool isK = by >= 4;
    const float* W = isK ? Wk : Wq;
    const float* bias = isK ? bk : bq;
    const int h = isK ? by - 4 : by;
    const int c0 = h * 64;
    const int rowBase = blockIdx.x * 64;
    const int b = rowBase >> 9;
    const int bh = b * HH + h;
    const int nb = rowBase & 511;

    __shared__ float xs[64][65];
    __shared__ float ws[64][64];

    const int t = threadIdx.x;
    const int tx = t & 15, ty = t >> 4;

    #pragma unroll
    for (int i = 0; i < 4; i++) {
        int lin4 = t + i * 256;
        int r = lin4 >> 4, c4 = (lin4 & 15) * 4;
        float4 v = *(const float4*)(x + rowBase * 64 + lin4 * 4);
        xs[r][c4] = v.x; xs[r][c4 + 1] = v.y; xs[r][c4 + 2] = v.z; xs[r][c4 + 3] = v.w;
        *(float4*)&ws[r][c4] = *(const float4*)(W + r * 256 + c0 + c4);
    }
    __syncthreads();

    float acc[4][4];
    #pragma unroll
    for (int i = 0; i < 4; i++)
        #pragma unroll
        for (int jj = 0; jj < 4; jj++) acc[i][jj] = 0.f;

    #pragma unroll 8
    for (int k = 0; k < 64; k++) {
        float a0 = xs[4 * ty + 0][k];
        float a1 = xs[4 * ty + 1][k];
        float a2 = xs[4 * ty + 2][k];
        float a3 = xs[4 * ty + 3][k];
        float4 bv = *(float4*)&ws[k][4 * tx];
        acc[0][0] += a0 * bv.x; acc[0][1] += a0 * bv.y; acc[0][2] += a0 * bv.z; acc[0][3] += a0 * bv.w;
        acc[1][0] += a1 * bv.x; acc[1][1] += a1 * bv.y; acc[1][2] += a1 * bv.z; acc[1][3] += a1 * bv.w;
        acc[2][0] += a2 * bv.x; acc[2][1] += a2 * bv.y; acc[2][2] += a2 * bv.z; acc[2][3] += a2 * bv.w;
        acc[3][0] += a3 * bv.x; acc[3][1] += a3 * bv.y; acc[3][2] += a3 * bv.z; acc[3][3] += a3 * bv.w;
    }

    float4 bb = *(const float4*)&bias[c0 + 4 * tx];
    const float sc = isK ? 1.0f : 0.125f;   // fold 1/sqrt(F) into q
    __nv_bfloat16* dh = isK ? g_kh : g_qh;
    __nv_bfloat16* dl = isK ? g_kl : g_ql;
    #pragma unroll
    for (int rr = 0; rr < 4; rr++) {
        int n = nb + 4 * ty + rr;
        size_t o = (size_t)(bh * NN + n) * FF + 4 * tx;
        float v0 = (acc[rr][0] + bb.x) * sc;
        float v1 = (acc[rr][1] + bb.y) * sc;
        float v2 = (acc[rr][2] + bb.z) * sc;
        float v3 = (acc[rr][3] + bb.w) * sc;
        __nv_bfloat16 h0 = __float2bfloat16(v0), h1 = __float2bfloat16(v1);
        __nv_bfloat16 h2 = __float2bfloat16(v2), h3 = __float2bfloat16(v3);
        *(__nv_bfloat162*)&dh[o]     = __halves2bfloat162(h0, h1);
        *(__nv_bfloat162*)&dh[o + 2] = __halves2bfloat162(h2, h3);
        *(__nv_bfloat162*)&dl[o] = __halves2bfloat162(
            __float2bfloat16(v0 - __bfloat162float(h0)),
            __float2bfloat16(v1 - __bfloat162float(h1)));
        *(__nv_bfloat162*)&dl[o + 2] = __halves2bfloat162(
            __float2bfloat16(v2 - __bfloat162float(h2)),
            __float2bfloat16(v3 - __bfloat162float(h3)));
    }
}

// ---------------- K3: HMMA scores + softmax + noradj reduce --------------
// grid (8 mtiles, H, B) = 128 blocks, 512 threads (16 warps).
// Warp w: m-strip (w>>2)*16, col-strip (w&3)*64 within each 256-col half.
// 3 independent accumulators break the MMA dependency chain (depth 12 -> 4).
#define QS 4608        // 64*72 elems
#define KS 18432       // 256*72 elems
#define ATTN_DSM 225280
__global__ __launch_bounds__(512, 1) void k_attn_mma() {
    extern __shared__ __align__(16) char dsm[];
    __nv_bfloat16* qh_s = (__nv_bfloat16*)dsm;
    __nv_bfloat16* ql_s = qh_s + QS;
    __nv_bfloat16* kh_s = qh_s + 2 * QS;
    __nv_bfloat16* kl_s = kh_s + KS;
    float* expb = (float*)(dsm + 92160);   // 64 x 520 fp32

    __shared__ float rsum[4][64];
    __shared__ float rinv[64];

    const int mtile = blockIdx.x, h = blockIdx.y, b = blockIdx.z;
    const int bh = b * HH + h;
    const int iBase = mtile * 64;
    const int tid = threadIdx.x;
    const int w = tid >> 5, lane = tid & 31;
    const int mrow = (w >> 2) * 16;     // warp's 16-row strip
    const int cq = w & 3;               // 64-col strip within a 256-col half
    const int r = lane >> 2, c = lane & 3;

    // --- load q (hi/lo) into smem: 512 uint4 each ---
    {
        const uint4* sh = (const uint4*)(g_qh + (size_t)(bh * NN + iBase) * FF);
        const uint4* sl = (const uint4*)(g_ql + (size_t)(bh * NN + iBase) * FF);
        int row = tid >> 3, c8 = tid & 7;
        *(uint4*)&qh_s[row * 72 + c8 * 8] = sh[tid];
        *(uint4*)&ql_s[row * 72 + c8 * 8] = sl[tid];
    }

    uint32_t qhA[4][4], qlA[4][4];
    float rs0 = 0.f, rs1 = 0.f;

    for (int half = 0; half < 2; half++) {
        __syncthreads();   // prev-half k reads done (and q stores visible)
        // --- load k half (hi/lo): 2048 uint4 each ---
        {
            const uint4* sh = (const uint4*)(g_kh + (size_t)(bh * NN + half * 256) * FF);
            const uint4* sl = (const uint4*)(g_kl + (size_t)(bh * NN + half * 256) * FF);
            #pragma unroll
            for (int i = 0; i < 4; i++) {
                int idx = tid + i * 512;      // 0..2047
                int row = idx >> 3, c8 = idx & 7;
                *(uint4*)&kh_s[row * 72 + c8 * 8] = sh[idx];
                *(uint4*)&kl_s[row * 72 + c8 * 8] = sl[idx];
            }
        }
        __syncthreads();

        if (half == 0) {
            #pragma unroll
            for (int kt = 0; kt < 4; kt++) {
                int col = kt * 16 + 2 * c;
                qhA[kt][0] = *(const uint32_t*)&qh_s[(mrow + r) * 72 + col];
                qhA[kt][1] = *(const uint32_t*)&qh_s[(mrow + r + 8) * 72 + col];
                qhA[kt][2] = *(const uint32_t*)&qh_s[(mrow + r) * 72 + col + 8];
                qhA[kt][3] = *(const uint32_t*)&qh_s[(mrow + r + 8) * 72 + col + 8];
                qlA[kt][0] = *(const uint32_t*)&ql_s[(mrow + r) * 72 + col];
                qlA[kt][1] = *(const uint32_t*)&ql_s[(mrow + r + 8) * 72 + col];
                qlA[kt][2] = *(const uint32_t*)&ql_s[(mrow + r) * 72 + col + 8];
                qlA[kt][3] = *(const uint32_t*)&ql_s[(mrow + r + 8) * 72 + col + 8];
            }
        }

        #pragma unroll 2
        for (int nt = 0; nt < 8; nt++) {
            const int jloc = cq * 64 + nt * 8 + r;    // local k row for B frag
            uint32_t khB[4][2], klB[4][2];
            #pragma unroll
            for (int kt = 0; kt < 4; kt++) {
                int col = kt * 16 + 2 * c;
                khB[kt][0] = *(const uint32_t*)&kh_s[jloc * 72 + col];
                khB[kt][1] = *(const uint32_t*)&kh_s[jloc * 72 + col + 8];
                klB[kt][0] = *(const uint32_t*)&kl_s[jloc * 72 + col];
                klB[kt][1] = *(const uint32_t*)&kl_s[jloc * 72 + col + 8];
            }
            float d0[4] = {0.f, 0.f, 0.f, 0.f};
            float d1[4] = {0.f, 0.f, 0.f, 0.f};
            float d2[4] = {0.f, 0.f, 0.f, 0.f};
            #pragma unroll
            for (int kt = 0; kt < 4; kt++) {
                mma16816(d0, qhA[kt], khB[kt]);
                mma16816(d1, qhA[kt], klB[kt]);
                mma16816(d2, qlA[kt], khB[kt]);
            }
            float e0 = __expf(d0[0] + d1[0] + d2[0]);
            float e1 = __expf(d0[1] + d1[1] + d2[1]);
            float e2 = __expf(d0[2] + d1[2] + d2[2]);
            float e3 = __expf(d0[3] + d1[3] + d2[3]);
            rs0 += e0 + e1;
            rs1 += e2 + e3;
            int gcol = half * 256 + cq * 64 + nt * 8 + 2 * c;
            *(float2*)&expb[(mrow + r) * 520 + gcol]     = make_float2(e0, e1);
            *(float2*)&expb[(mrow + r + 8) * 520 + gcol] = make_float2(e2, e3);
        }
    }

    // --- rowsums: reduce over quad, combine 4 col strips ---
    rs0 += __shfl_xor_sync(0xffffffffu, rs0, 1);
    rs0 += __shfl_xor_sync(0xffffffffu, rs0, 2);
    rs1 += __shfl_xor_sync(0xffffffffu, rs1, 1);
    rs1 += __shfl_xor_sync(0xffffffffu, rs1, 2);
    if ((lane & 3) == 0) {
        rsum[cq][mrow + r] = rs0;
        rsum[cq][mrow + r + 8] = rs1;
    }
    __syncthreads();
    if (tid < 64)
        rinv[tid] = 1.0f / (rsum[0][tid] + rsum[1][tid] + rsum[2][tid] + rsum[3][tid]);
    __syncthreads();

    // --- T partial: one column per thread, deterministic ---
    {
        const float* np = g_nor + (size_t)iBase * NN;
        float a0 = 0.f;
        #pragma unroll 4
        for (int i = 0; i < 64; i++)
            a0 += np[i * NN + tid] * (expb[i * 520 + tid] * rinv[i]);
        g_Tpart[mtile * (BB * HH * NN) + bh * NN + tid] = a0;
    }
}

// ---------------- K3b: reduce T partials + column sums c ----------------
__global__ void k_red() {
    if (blockIdx.x < 16) {
        int v = blockIdx.x * 512 + threadIdx.x;
        float s = 0.f;
        #pragma unroll
        for (int ch = 0; ch < NCHT; ch++) s += g_Tpart[ch * (BB * HH * NN) + v];
        g_T[v] = s;
    } else {
        int j = threadIdx.x;
        float s = 0.f;
        #pragma unroll
        for (int p = 0; p < 128; p++) s += g_cpart[p * NN + j];
        g_c[j] = s;
    }
}

// ---------------- K4: out = relu((noradj @ (x*S)) @ Wfc + bfc), fused ----
__global__ __launch_bounds__(256) void k_out(const float* __restrict__ x,
                                             const float* __restrict__ Wlin,
                                             const float* __restrict__ blin,
                                             const float* __restrict__ Wfc,
                                             const float* __restrict__ bfc,
                                             float* __restrict__ out) {
    const int iBase = blockIdx.x * 16;
    const int b = blockIdx.y;
    const int t = threadIdx.x;
    const int il = t >> 4, fq = t & 15;

    __shared__ float sxs[32][64];
    __shared__ float nrs[32][17];
    __shared__ float wfcs[64 * 64];
    __shared__ float tmp[16][68];
    __shared__ float Ts[HH * NN];
    __shared__ float cs[NN];
    __shared__ float wlins[HH][64];
    __shared__ float blins[64];

    #pragma unroll
    for (int i = 0; i < 4; i++) ((float4*)wfcs)[t + i * 256] = ((const float4*)Wfc)[t + i * 256];
    #pragma unroll
    for (int i = 0; i < 2; i++) ((float4*)Ts)[t + i * 256] = ((const float4*)(g_T + b * HH * NN))[t + i * 256];
    if (t < 128) ((float4*)cs)[t] = ((const float4*)g_c)[t];
    if (t < 64)  ((float4*)wlins)[t] = ((const float4*)Wlin)[t];
    if (t < 16)  ((float4*)blins)[t] = ((const float4*)blin)[t];
    __syncthreads();

    unsigned long long acc0 = 0ull, acc1 = 0ull;
    for (int j0 = 0; j0 < NN; j0 += 32) {
        #pragma unroll
        for (int i = 0; i < 2; i++) {
            int lin = t + i * 256;
            int jj = lin >> 4, f4 = (lin & 15) * 4;
            int jg = j0 + jj;
            float4 xv = *(const float4*)(x + ((b * NN) + jg) * FF + f4);
            float4 bl = *(const float4*)&blins[f4];
            float cj = cs[jg];
            float4 s4;
            s4.x = cj * bl.x; s4.y = cj * bl.y; s4.z = cj * bl.z; s4.w = cj * bl.w;
            #pragma unroll
            for (int hh = 0; hh < HH; hh++) {
                float tv = Ts[hh * NN + jg];
                float4 wl = *(const float4*)&wlins[hh][f4];
                s4.x += tv * wl.x; s4.y += tv * wl.y; s4.z += tv * wl.z; s4.w += tv * wl.w;
            }
            *(float4*)&sxs[jj][f4] =
                make_float4(xv.x * s4.x, xv.y * s4.y, xv.z * s4.z, xv.w * s4.w);
            int ii = lin >> 5, jjn = lin & 31;
            nrs[jjn][ii] = g_nor[(iBase + ii) * NN + j0 + jjn];
        }
        __syncthreads();
        #pragma unroll
        for (int jj = 0; jj < 32; jj++) {
            float nrv = nrs[jj][il];
            unsigned long long nr2 = f2pack(nrv, nrv);
            const unsigned long long* sp = (const unsigned long long*)&sxs[jj][4 * fq];
            f2fma(acc0, nr2, sp[0]);
            f2fma(acc1, nr2, sp[1]);
        }
        __syncthreads();
    }

    float v0, v1, v2, v3;
    f2unpack(acc0, v0, v1);
    f2unpack(acc1, v2, v3);
    tmp[il][4 * fq] = v0; tmp[il][4 * fq + 1] = v1;
    tmp[il][4 * fq + 2] = v2; tmp[il][4 * fq + 3] = v3;
    __syncthreads();

    float4 bb = *(const float4*)&bfc[4 * fq];
    unsigned long long o0 = f2pack(bb.x, bb.y);
    unsigned long long o1 = f2pack(bb.z, bb.w);
    #pragma unroll
    for (int ff = 0; ff < 64; ff++) {
        float tv = tmp[il][ff];
        unsigned long long tv2 = f2pack(tv, tv);
        const unsigned long long* wp = (const unsigned long long*)&wfcs[ff * 64 + 4 * fq];
        f2fma(o0, tv2, wp[0]);
        f2fma(o1, tv2, wp[1]);
    }
    float r0, r1, r2, r3;
    f2unpack(o0, r0, r1);
    f2unpack(o1, r2, r3);
    *(float4*)&out[((b * NN) + iBase + il) * FF + 4 * fq] =
        make_float4(fmaxf(r0, 0.f), fmaxf(r1, 0.f), fmaxf(r2, 0.f), fmaxf(r3, 0.f));
}

// ---------------- launch ----------------
extern "C" void kernel_launch(void* const* d_in, const int* in_sizes, int n_in,
                              void* d_out, int out_size) {
    const float* x    = (const float*)d_in[0];
    const float* adj  = (const float*)d_in[1];
    const float* Wq   = (const float*)d_in[2];
    const float* bq   = (const float*)d_in[3];
    const float* Wk   = (const float*)d_in[4];
    const float* bk   = (const float*)d_in[5];
    const float* Wlin = (const float*)d_in[6];
    const float* blin = (const float*)d_in[7];
    const float* Wfc  = (const float*)d_in[8];
    const float* bfc  = (const float*)d_in[9];
    float* out = (float*)d_out;

    static int attr_set = 0;
    if (!attr_set) {
        cudaFuncSetAttribute(k_attn_mma,
                             cudaFuncAttributeMaxDynamicSharedMemorySize, ATTN_DSM);
        attr_set = 1;
    }

    k_deg<<<NN, 256>>>(adj);
    k_nor<<<128, 512>>>(adj);
    k_proj<<<dim3(32, 8), 256>>>(x, Wq, bq, Wk, bk);
    k_attn_mma<<<dim3(8, HH, BB), 512, ATTN_DSM>>>();
    k_red<<<17, 512>>>();
    k_out<<<dim3(32, BB), 256>>>(x, Wlin, blin, Wfc, bfc, out);
}